// round 1
// baseline (speedup 1.0000x reference)
#include <cuda_runtime.h>
#include <math.h>

#define BDIM 32
#define CDIM 256
#define TDIM 64
#define VDIM 50
#define TOK (BDIM*TDIM*VDIM)   // 102400
#define C2  512
#define C4  1024

// ---------------- scratch (global memory via __device__ arrays) ----------------
__device__ float g_xt  [TOK*CDIM];  // x token-major (skip)
__device__ float g_xln [TOK*CDIM];  // LN1(x)
__device__ float g_f   [TOK*C2];    // map output
__device__ float g_cat [TOK*CDIM];  // concat of branch outputs
__device__ float g_out1[TOK*CDIM];  // proj + skip
__device__ float g_ln2 [TOK*CDIM];
__device__ float g_h   [TOK*C4];    // mlp hidden
__device__ float g_out2[TOK*CDIM];  // final token-major

// ---------------- transpose x (B,C,T,V) -> token-major (B,T,V,C) ----------------
__global__ __launch_bounds__(256) void k_trans(const float* __restrict__ x) {
    int bt = blockIdx.x;          // B*T
    int cc = blockIdx.y;          // 4 chunks of 64 channels
    int bb = bt / TDIM, t = bt % TDIM;
    __shared__ float s[64][51];
    int tid = threadIdx.x;
    const float* xp = x + ((size_t)bb*CDIM + cc*64)*(TDIM*VDIM) + (size_t)t*VDIM;
    for (int i = tid; i < 64*VDIM; i += 256) {
        int c = i / VDIM, v = i % VDIM;
        s[c][v] = xp[(size_t)c*TDIM*VDIM + v];
    }
    __syncthreads();
    size_t tok0 = (size_t)bt*VDIM;
    for (int i = tid; i < 64*VDIM; i += 256) {
        int v = i >> 6, c = i & 63;
        g_xt[(tok0+v)*CDIM + cc*64 + c] = s[c][v];
    }
}

// ---------------- generic LayerNorm over contiguous 256-d rows ----------------
__global__ __launch_bounds__(256) void k_ln(const float* __restrict__ src,
                                            float* __restrict__ dst,
                                            const float* __restrict__ w,
                                            const float* __restrict__ b) {
    size_t m = blockIdx.x;
    int c = threadIdx.x;
    float q = src[m*CDIM + c];
    float s1 = q, s2 = q*q;
    #pragma unroll
    for (int o = 16; o; o >>= 1) {
        s1 += __shfl_xor_sync(0xffffffffu, s1, o);
        s2 += __shfl_xor_sync(0xffffffffu, s2, o);
    }
    __shared__ float red[18];
    int wid = c >> 5, lid = c & 31;
    if (lid == 0) { red[wid] = s1; red[8+wid] = s2; }
    __syncthreads();
    if (c == 0) {
        float a1 = 0.f, a2 = 0.f;
        for (int i = 0; i < 8; i++) { a1 += red[i]; a2 += red[8+i]; }
        float mean = a1 * (1.0f/CDIM);
        float var  = a2 * (1.0f/CDIM) - mean*mean;
        red[16] = mean;
        red[17] = rsqrtf(var + 1e-5f);
    }
    __syncthreads();
    dst[m*CDIM + c] = (q - red[16]) * red[17] * w[c] + b[c];
}

// ---------------- fp32 tiled GEMM 128x128x8, 8x8 per thread ----------------
// C[M,N] = A[M,K] @ B[K,N] + bias[N]  (+ epilogue)
// EPI: 0 = bias, 1 = bias + extra[m,n], 2 = bias + exact GELU
template<int EPI>
__global__ __launch_bounds__(256) void k_gemm(const float* __restrict__ A,
                                              const float* __restrict__ Bw,
                                              const float* __restrict__ bias,
                                              const float* __restrict__ extra,
                                              float* __restrict__ C,
                                              int M, int N, int K) {
    __shared__ float As[8][128];
    __shared__ float Bs[8][128];
    int tid = threadIdx.x;
    int m0 = blockIdx.y * 128, n0 = blockIdx.x * 128;
    int ar = tid >> 1, ac = (tid & 1) * 4;
    int br = tid >> 5, bc = (tid & 31) * 4;
    int ty = tid >> 4, tx = tid & 15;

    float acc[8][8];
    #pragma unroll
    for (int i = 0; i < 8; i++)
        #pragma unroll
        for (int j = 0; j < 8; j++) acc[i][j] = 0.f;

    for (int k0 = 0; k0 < K; k0 += 8) {
        float4 av = *(const float4*)&A[(size_t)(m0+ar)*K + k0 + ac];
        As[ac+0][ar] = av.x; As[ac+1][ar] = av.y;
        As[ac+2][ar] = av.z; As[ac+3][ar] = av.w;
        *(float4*)&Bs[br][bc] = *(const float4*)&Bw[(size_t)(k0+br)*N + n0 + bc];
        __syncthreads();
        #pragma unroll
        for (int k = 0; k < 8; k++) {
            float a[8], bf[8];
            *(float4*)(a)   = *(float4*)&As[k][ty*8];
            *(float4*)(a+4) = *(float4*)&As[k][ty*8+4];
            *(float4*)(bf)   = *(float4*)&Bs[k][tx*8];
            *(float4*)(bf+4) = *(float4*)&Bs[k][tx*8+4];
            #pragma unroll
            for (int i = 0; i < 8; i++)
                #pragma unroll
                for (int j = 0; j < 8; j++) acc[i][j] += a[i]*bf[j];
        }
        __syncthreads();
    }

    #pragma unroll
    for (int i = 0; i < 8; i++) {
        size_t m = (size_t)(m0 + ty*8 + i);
        float vout[8];
        #pragma unroll
        for (int j = 0; j < 8; j++) {
            int n = n0 + tx*8 + j;
            float v = acc[i][j] + bias[n];
            if (EPI == 1) v += extra[m*N + n];
            if (EPI == 2) v = 0.5f * v * (1.0f + erff(v * 0.70710678118654752f));
            vout[j] = v;
        }
        *(float4*)&C[m*N + n0 + tx*8]     = *(float4*)(vout);
        *(float4*)&C[m*N + n0 + tx*8 + 4] = *(float4*)(vout+4);
    }
}

// ---------------- gconv branch: channels 0..63 of concat ----------------
__global__ __launch_bounds__(256) void k_gconv(const float* __restrict__ gw) {
    int bt = blockIdx.x;            // B*T
    __shared__ float fg[VDIM][64];
    int tid = threadIdx.x;
    size_t tok0 = (size_t)bt * VDIM;
    for (int i = tid; i < VDIM*64; i += 256) {
        int u = i >> 6, c = i & 63;
        fg[u][c] = g_f[(tok0+u)*C2 + c];
    }
    __syncthreads();
    for (int i = tid; i < VDIM*64; i += 256) {
        int v = i >> 6, ch = i & 63;
        int g = ch >> 3;
        const float* gwp = gw + ((size_t)g*VDIM + v)*VDIM;
        float acc = 0.f;
        #pragma unroll
        for (int u = 0; u < VDIM; u++) acc += fg[u][ch] * gwp[u];
        g_cat[(tok0+v)*CDIM + ch] = acc;
    }
}

// ---------------- grouped temporal conv branch: channels 64..127 ----------------
__global__ __launch_bounds__(256) void k_tconv(const float* __restrict__ w,
                                               const float* __restrict__ bias) {
    int bt = blockIdx.x;
    int bb = bt / TDIM, t = bt % TDIM;
    __shared__ float ws[56*64];     // [ic*7+dt][o]
    int tid = threadIdx.x;
    for (int i = tid; i < 64*56; i += 256) {
        int o = i / 56, r = i % 56;
        ws[r*64 + o] = w[i];
    }
    __syncthreads();
    size_t tok0 = (size_t)bt * VDIM;
    for (int i = tid; i < VDIM*64; i += 256) {
        int v = i >> 6, o = i & 63;
        int g = o >> 3;
        float acc = bias[o];
        #pragma unroll
        for (int dt = 0; dt < 7; dt++) {
            int tt = t + dt - 3;
            if (tt < 0 || tt >= TDIM) continue;
            size_t base = ((size_t)(bb*TDIM + tt)*VDIM + v)*C2 + 64 + g*8;
            #pragma unroll
            for (int ic = 0; ic < 8; ic++)
                acc += g_f[base + ic] * ws[(ic*7 + dt)*64 + o];
        }
        g_cat[(tok0+v)*CDIM + 64 + o] = acc;
    }
}

// ---------------- windowed hyperbolic linear attention: channels 128..255 ----------------
__global__ __launch_bounds__(128) void k_attn() {
    int wb = blockIdx.x;                 // 4 * B * 40 windows
    int mode = wb / (BDIM*40);
    int rem  = wb % (BDIM*40);
    int bb = rem / 40;
    int wwin = rem % 40;
    int i0 = wwin / 5, i1 = wwin % 5;

    __shared__ float X[80][97];
    __shared__ float kv[4][8][8];
    __shared__ float O[80][33];
    __shared__ int   toks[80];
    int tid = threadIdx.x;

    if (tid < 80) {
        int a = tid / 10, e = tid % 10;
        int t, v;
        if      (mode == 0) { t = i0*8 + a; v = i1*10 + e; }
        else if (mode == 1) { t = i0*8 + a; v = e*5 + i1;  }
        else if (mode == 2) { t = a*8 + i0; v = i1*10 + e; }
        else                { t = a*8 + i0; v = e*5 + i1;  }
        toks[tid] = (bb*TDIM + t)*VDIM + v;
    }
    __syncthreads();

    int cb = 128 + mode*96;
    for (int i = tid; i < 80*96; i += 128) {
        int n = i / 96, c = i % 96;
        X[n][c] = g_f[(size_t)toks[n]*C2 + cb + c];
    }
    __syncthreads();

    // euclidean -> poincare : scale by tanh(||x||)/||x||
    if (tid < 80) {
        float sq = 0.f;
        #pragma unroll 8
        for (int c = 0; c < 96; c++) { float q = X[tid][c]; sq += q*q; }
        float nrm = fmaxf(sqrtf(sq), 1e-10f);
        float sc = tanhf(nrm) / nrm;
        #pragma unroll 8
        for (int c = 0; c < 96; c++) X[tid][c] *= sc;
    }
    __syncthreads();

    // raw kv[h][d][e] = sum_n k[n,h,d]*v[n,h,e]
    for (int i = tid; i < 256; i += 128) {
        int h = i >> 6, d = (i >> 3) & 7, e = i & 7;
        float acc = 0.f;
        for (int n = 0; n < 80; n++)
            acc += X[n][32 + h*8 + d] * X[n][64 + h*8 + e];
        kv[h][d][e] = acc;
    }
    __syncthreads();

    // softmax over e per (h,d)
    if (tid < 32) {
        int h = tid >> 3, d = tid & 7;
        float mx = -1e30f;
        #pragma unroll
        for (int e = 0; e < 8; e++) mx = fmaxf(mx, kv[h][d][e]);
        float s = 0.f;
        #pragma unroll
        for (int e = 0; e < 8; e++) { float q = expf(kv[h][d][e] - mx); s += q; kv[h][d][e] = q; }
        float inv = 1.0f / s;
        #pragma unroll
        for (int e = 0; e < 8; e++) kv[h][d][e] *= inv;
    }
    __syncthreads();

    // attn[n, h*8+m] = 0.5 * sum_i q[n,h,i]*kv[h][m][i]
    for (int i = tid; i < 80*32; i += 128) {
        int n = i >> 5, o = i & 31;
        int h = o >> 3, mm = o & 7;
        float acc = 0.f;
        #pragma unroll
        for (int e = 0; e < 8; e++) acc += X[n][h*8 + e] * kv[h][mm][e];
        O[n][o] = 0.5f * acc;
    }
    __syncthreads();

    // poincare -> euclidean: scale by arctanh(-n)/n with n clipped, then scatter
    if (tid < 80) {
        float sq = 0.f;
        #pragma unroll
        for (int c = 0; c < 32; c++) { float q = O[tid][c]; sq += q*q; }
        float nrm = fminf(fmaxf(sqrtf(sq), 1e-10f), 1.0f - 1e-5f);
        float sc = atanhf(-nrm) / nrm;
        size_t base = (size_t)toks[tid]*CDIM + 128 + mode*32;
        #pragma unroll
        for (int c = 0; c < 32; c++) g_cat[base + c] = O[tid][c] * sc;
    }
}

// ---------------- final transpose token-major -> (B,C,T,V) ----------------
__global__ __launch_bounds__(256) void k_out(float* __restrict__ out) {
    int blk = blockIdx.x;           // B*T*2
    int vh = blk & 1;
    int bt = blk >> 1;
    int bb = bt / TDIM, t = bt % TDIM;
    __shared__ float s[25][257];
    int tid = threadIdx.x;
    size_t tok0 = (size_t)bt*VDIM + vh*25;
    for (int i = tid; i < 25*CDIM; i += 256) {
        int v = i >> 8, c = i & 255;
        s[v][c] = g_out2[(tok0 + v)*CDIM + c];
    }
    __syncthreads();
    for (int i = tid; i < 25*CDIM; i += 256) {
        int c = i / 25, v = i % 25;
        out[(((size_t)bb*CDIM + c)*TDIM + t)*VDIM + vh*25 + v] = s[v][c];
    }
}

// ---------------- launch ----------------
extern "C" void kernel_launch(void* const* d_in, const int* in_sizes, int n_in,
                              void* d_out, int out_size) {
    const float* x       = (const float*)d_in[0];
    const float* n1w     = (const float*)d_in[1];
    const float* n1b     = (const float*)d_in[2];
    const float* map_w   = (const float*)d_in[3];
    const float* map_b   = (const float*)d_in[4];
    const float* gconv   = (const float*)d_in[5];
    const float* tconv_w = (const float*)d_in[6];
    const float* tconv_b = (const float*)d_in[7];
    const float* proj_w  = (const float*)d_in[8];
    const float* proj_b  = (const float*)d_in[9];
    const float* n2w     = (const float*)d_in[10];
    const float* n2b     = (const float*)d_in[11];
    const float* mlp_w1  = (const float*)d_in[12];
    const float* mlp_b1  = (const float*)d_in[13];
    const float* mlp_w2  = (const float*)d_in[14];
    const float* mlp_b2  = (const float*)d_in[15];
    float* out = (float*)d_out;

    float *p_xt, *p_xln, *p_f, *p_cat, *p_out1, *p_ln2, *p_h, *p_out2;
    cudaGetSymbolAddress((void**)&p_xt,   g_xt);
    cudaGetSymbolAddress((void**)&p_xln,  g_xln);
    cudaGetSymbolAddress((void**)&p_f,    g_f);
    cudaGetSymbolAddress((void**)&p_cat,  g_cat);
    cudaGetSymbolAddress((void**)&p_out1, g_out1);
    cudaGetSymbolAddress((void**)&p_ln2,  g_ln2);
    cudaGetSymbolAddress((void**)&p_h,    g_h);
    cudaGetSymbolAddress((void**)&p_out2, g_out2);

    // 1) transpose to token-major
    k_trans<<<dim3(BDIM*TDIM, 4), 256>>>(x);
    // 2) LN1
    k_ln<<<TOK, 256>>>(p_xt, p_xln, n1w, n1b);
    // 3) map GEMM: [TOK,256] @ [256,512]
    k_gemm<0><<<dim3(C2/128, TOK/128), 256>>>(p_xln, map_w, map_b, nullptr, p_f, TOK, C2, CDIM);
    // 4) gconv branch
    k_gconv<<<BDIM*TDIM, 256>>>(gconv);
    // 5) temporal conv branch
    k_tconv<<<BDIM*TDIM, 256>>>(tconv_w, tconv_b);
    // 6) 4-mode windowed attention
    k_attn<<<4*BDIM*40, 128>>>();
    // 7) proj GEMM + skip
    k_gemm<1><<<dim3(CDIM/128, TOK/128), 256>>>(p_cat, proj_w, proj_b, p_xt, p_out1, TOK, CDIM, CDIM);
    // 8) LN2
    k_ln<<<TOK, 256>>>(p_out1, p_ln2, n2w, n2b);
    // 9) mlp1 GEMM + gelu
    k_gemm<2><<<dim3(C4/128, TOK/128), 256>>>(p_ln2, mlp_w1, mlp_b1, nullptr, p_h, TOK, C4, CDIM);
    // 10) mlp2 GEMM + residual
    k_gemm<1><<<dim3(CDIM/128, TOK/128), 256>>>(p_h, mlp_w2, mlp_b2, p_out1, p_out2, TOK, CDIM, C4);
    // 11) transpose to output layout
    k_out<<<BDIM*TDIM*2, 256>>>(out);
}

// round 3
// speedup vs baseline: 1.7364x; 1.7364x over previous
#include <cuda_runtime.h>
#include <math.h>

#define BDIM 32
#define CDIM 256
#define TDIM 64
#define VDIM 50
#define TOK (BDIM*TDIM*VDIM)   // 102400
#define C2  512
#define C4  1024

// ---------------- scratch ----------------
__device__ float g_xt  [TOK*CDIM];
__device__ float g_xln [TOK*CDIM];
__device__ float g_f   [TOK*C2];
__device__ float g_cat [TOK*CDIM];
__device__ float g_out1[TOK*CDIM];
__device__ float g_ln2 [TOK*CDIM];
__device__ float g_h   [TOK*C4];
__device__ float g_out2[TOK*CDIM];

__device__ __forceinline__ unsigned f2tf(float f) {
    unsigned r;
    asm("cvt.rna.tf32.f32 %0, %1;" : "=r"(r) : "f"(f));
    return r;
}

// ---------------- transpose x (B,C,T,V) -> token-major ----------------
__global__ __launch_bounds__(256) void k_trans(const float* __restrict__ x) {
    int bt = blockIdx.x;
    int cc = blockIdx.y;
    int bb = bt / TDIM, t = bt % TDIM;
    __shared__ float s[64][51];
    int tid = threadIdx.x;
    const float* xp = x + ((size_t)bb*CDIM + cc*64)*(TDIM*VDIM) + (size_t)t*VDIM;
    for (int i = tid; i < 64*VDIM; i += 256) {
        int c = i / VDIM, v = i % VDIM;
        s[c][v] = xp[(size_t)c*TDIM*VDIM + v];
    }
    __syncthreads();
    size_t tok0 = (size_t)bt*VDIM;
    for (int i = tid; i < 64*VDIM; i += 256) {
        int v = i >> 6, c = i & 63;
        g_xt[(tok0+v)*CDIM + cc*64 + c] = s[c][v];
    }
}

// ---------------- LayerNorm ----------------
__global__ __launch_bounds__(256) void k_ln(const float* __restrict__ src,
                                            float* __restrict__ dst,
                                            const float* __restrict__ w,
                                            const float* __restrict__ b) {
    size_t m = blockIdx.x;
    int c = threadIdx.x;
    float q = src[m*CDIM + c];
    float s1 = q, s2 = q*q;
    #pragma unroll
    for (int o = 16; o; o >>= 1) {
        s1 += __shfl_xor_sync(0xffffffffu, s1, o);
        s2 += __shfl_xor_sync(0xffffffffu, s2, o);
    }
    __shared__ float red[18];
    int wid = c >> 5, lid = c & 31;
    if (lid == 0) { red[wid] = s1; red[8+wid] = s2; }
    __syncthreads();
    if (c == 0) {
        float a1 = 0.f, a2 = 0.f;
        for (int i = 0; i < 8; i++) { a1 += red[i]; a2 += red[8+i]; }
        float mean = a1 * (1.0f/CDIM);
        float var  = a2 * (1.0f/CDIM) - mean*mean;
        red[16] = mean;
        red[17] = rsqrtf(var + 1e-5f);
    }
    __syncthreads();
    dst[m*CDIM + c] = (q - red[16]) * red[17] * w[c] + b[c];
}

// ---------------- TF32 tensor-core GEMM 128x128x16 ----------------
// C[M,N] = A[M,K] @ B[K,N] + bias  (EPI: 0 bias, 1 +extra, 2 gelu)
// 8 warps in 2(m) x 4(n); each warp 64x32 via 4x4 m16n8k8 mmas.
#define SMS 132   // padded smem row stride
template<int EPI>
__global__ __launch_bounds__(256, 2) void k_gemm_tc(const float* __restrict__ A,
                                                    const float* __restrict__ Bw,
                                                    const float* __restrict__ bias,
                                                    const float* __restrict__ extra,
                                                    float* __restrict__ C,
                                                    int M, int N, int K) {
    __shared__ unsigned As[16*SMS];
    __shared__ unsigned Bs[16*SMS];
    int tid  = threadIdx.x;
    int lane = tid & 31, warp = tid >> 5;
    int wm = warp >> 2, wn = warp & 3;       // warp tile: rows wm*64, cols wn*32
    int m0 = blockIdx.y * 128, n0 = blockIdx.x * 128;
    int r = lane >> 2, c = lane & 3;         // groupID, threadID-in-group

    float acc[4][4][4];
    #pragma unroll
    for (int i = 0; i < 4; i++)
        #pragma unroll
        for (int j = 0; j < 4; j++)
            #pragma unroll
            for (int q = 0; q < 4; q++) acc[i][j][q] = 0.f;

    for (int k0 = 0; k0 < K; k0 += 16) {
        // A tile 128x16 (transposed into As[k][m]); B tile 16x128 (Bs[k][n])
        #pragma unroll
        for (int it = 0; it < 2; it++) {
            int idx = tid + it*256;
            int am = idx >> 2, aq = (idx & 3) * 4;
            float4 av = *(const float4*)&A[(size_t)(m0+am)*K + k0 + aq];
            As[(aq+0)*SMS + am] = f2tf(av.x);
            As[(aq+1)*SMS + am] = f2tf(av.y);
            As[(aq+2)*SMS + am] = f2tf(av.z);
            As[(aq+3)*SMS + am] = f2tf(av.w);
            int bk = idx >> 5, bq = (idx & 31) * 4;   // FIXED: 16 rows x 128 cols
            float4 bv = *(const float4*)&Bw[(size_t)(k0+bk)*N + n0 + bq];
            Bs[bk*SMS + bq+0] = f2tf(bv.x);
            Bs[bk*SMS + bq+1] = f2tf(bv.y);
            Bs[bk*SMS + bq+2] = f2tf(bv.z);
            Bs[bk*SMS + bq+3] = f2tf(bv.w);
        }
        __syncthreads();
        #pragma unroll
        for (int kk = 0; kk < 16; kk += 8) {
            unsigned af[4][4], bf[4][2];
            #pragma unroll
            for (int i = 0; i < 4; i++) {
                int mb = wm*64 + i*16 + r;
                af[i][0] = As[(kk+c  )*SMS + mb];
                af[i][1] = As[(kk+c  )*SMS + mb + 8];
                af[i][2] = As[(kk+c+4)*SMS + mb];
                af[i][3] = As[(kk+c+4)*SMS + mb + 8];
            }
            #pragma unroll
            for (int j = 0; j < 4; j++) {
                int nb = wn*32 + j*8 + r;
                bf[j][0] = Bs[(kk+c  )*SMS + nb];
                bf[j][1] = Bs[(kk+c+4)*SMS + nb];
            }
            #pragma unroll
            for (int i = 0; i < 4; i++)
                #pragma unroll
                for (int j = 0; j < 4; j++) {
                    asm volatile(
                        "mma.sync.aligned.m16n8k8.row.col.f32.tf32.tf32.f32 "
                        "{%0,%1,%2,%3}, {%4,%5,%6,%7}, {%8,%9}, {%0,%1,%2,%3};"
                        : "+f"(acc[i][j][0]), "+f"(acc[i][j][1]),
                          "+f"(acc[i][j][2]), "+f"(acc[i][j][3])
                        : "r"(af[i][0]), "r"(af[i][1]), "r"(af[i][2]), "r"(af[i][3]),
                          "r"(bf[j][0]), "r"(bf[j][1]));
                }
        }
        __syncthreads();
    }

    #pragma unroll
    for (int i = 0; i < 4; i++) {
        #pragma unroll
        for (int j = 0; j < 4; j++) {
            int row0 = m0 + wm*64 + i*16 + r;
            int col  = n0 + wn*32 + j*8 + c*2;
            float b0 = bias[col], b1 = bias[col+1];
            #pragma unroll
            for (int h = 0; h < 2; h++) {
                size_t mrow = (size_t)(row0 + h*8);
                float v0 = acc[i][j][2*h+0] + b0;
                float v1 = acc[i][j][2*h+1] + b1;
                if (EPI == 1) {
                    const float2 e = *(const float2*)&extra[mrow*N + col];
                    v0 += e.x; v1 += e.y;
                }
                if (EPI == 2) {
                    v0 = 0.5f * v0 * (1.0f + erff(v0 * 0.70710678118654752f));
                    v1 = 0.5f * v1 * (1.0f + erff(v1 * 0.70710678118654752f));
                }
                float2 o; o.x = v0; o.y = v1;
                *(float2*)&C[mrow*N + col] = o;
            }
        }
    }
}

// ---------------- gconv branch ----------------
__global__ __launch_bounds__(256) void k_gconv(const float* __restrict__ gw) {
    int bt = blockIdx.x;
    __shared__ float fg[VDIM][64];
    int tid = threadIdx.x;
    size_t tok0 = (size_t)bt * VDIM;
    for (int i = tid; i < VDIM*64; i += 256) {
        int u = i >> 6, c = i & 63;
        fg[u][c] = g_f[(tok0+u)*C2 + c];
    }
    __syncthreads();
    for (int i = tid; i < VDIM*64; i += 256) {
        int v = i >> 6, ch = i & 63;
        int g = ch >> 3;
        const float* gwp = gw + ((size_t)g*VDIM + v)*VDIM;
        float acc = 0.f;
        #pragma unroll
        for (int u = 0; u < VDIM; u++) acc += fg[u][ch] * gwp[u];
        g_cat[(tok0+v)*CDIM + ch] = acc;
    }
}

// ---------------- grouped temporal conv branch ----------------
__global__ __launch_bounds__(256) void k_tconv(const float* __restrict__ w,
                                               const float* __restrict__ bias) {
    int bt = blockIdx.x;
    int bb = bt / TDIM, t = bt % TDIM;
    __shared__ float ws[56*64];
    int tid = threadIdx.x;
    for (int i = tid; i < 64*56; i += 256) {
        int o = i / 56, r = i % 56;
        ws[r*64 + o] = w[i];
    }
    __syncthreads();
    size_t tok0 = (size_t)bt * VDIM;
    for (int i = tid; i < VDIM*64; i += 256) {
        int v = i >> 6, o = i & 63;
        int g = o >> 3;
        float acc = bias[o];
        #pragma unroll
        for (int dt = 0; dt < 7; dt++) {
            int tt = t + dt - 3;
            if (tt < 0 || tt >= TDIM) continue;
            size_t base = ((size_t)(bb*TDIM + tt)*VDIM + v)*C2 + 64 + g*8;
            #pragma unroll
            for (int ic = 0; ic < 8; ic++)
                acc += g_f[base + ic] * ws[(ic*7 + dt)*64 + o];
        }
        g_cat[(tok0+v)*CDIM + 64 + o] = acc;
    }
}

// ---------------- windowed hyperbolic linear attention ----------------
__global__ __launch_bounds__(128) void k_attn() {
    int wb = blockIdx.x;
    int mode = wb / (BDIM*40);
    int rem  = wb % (BDIM*40);
    int bb = rem / 40;
    int wwin = rem % 40;
    int i0 = wwin / 5, i1 = wwin % 5;

    __shared__ float X[80][97];
    __shared__ float kv[4][8][8];
    __shared__ float O[80][33];
    __shared__ int   toks[80];
    int tid = threadIdx.x;

    if (tid < 80) {
        int a = tid / 10, e = tid % 10;
        int t, v;
        if      (mode == 0) { t = i0*8 + a; v = i1*10 + e; }
        else if (mode == 1) { t = i0*8 + a; v = e*5 + i1;  }
        else if (mode == 2) { t = a*8 + i0; v = i1*10 + e; }
        else                { t = a*8 + i0; v = e*5 + i1;  }
        toks[tid] = (bb*TDIM + t)*VDIM + v;
    }
    __syncthreads();

    int cb = 128 + mode*96;
    for (int i = tid; i < 80*96; i += 128) {
        int n = i / 96, c = i % 96;
        X[n][c] = g_f[(size_t)toks[n]*C2 + cb + c];
    }
    __syncthreads();

    if (tid < 80) {
        float sq = 0.f;
        #pragma unroll 8
        for (int c = 0; c < 96; c++) { float q = X[tid][c]; sq += q*q; }
        float nrm = fmaxf(sqrtf(sq), 1e-10f);
        float sc = tanhf(nrm) / nrm;
        #pragma unroll 8
        for (int c = 0; c < 96; c++) X[tid][c] *= sc;
    }
    __syncthreads();

    for (int i = tid; i < 256; i += 128) {
        int h = i >> 6, d = (i >> 3) & 7, e = i & 7;
        float acc = 0.f;
        for (int n = 0; n < 80; n++)
            acc += X[n][32 + h*8 + d] * X[n][64 + h*8 + e];
        kv[h][d][e] = acc;
    }
    __syncthreads();

    if (tid < 32) {
        int h = tid >> 3, d = tid & 7;
        float mx = -1e30f;
        #pragma unroll
        for (int e = 0; e < 8; e++) mx = fmaxf(mx, kv[h][d][e]);
        float s = 0.f;
        #pragma unroll
        for (int e = 0; e < 8; e++) { float q = expf(kv[h][d][e] - mx); s += q; kv[h][d][e] = q; }
        float inv = 1.0f / s;
        #pragma unroll
        for (int e = 0; e < 8; e++) kv[h][d][e] *= inv;
    }
    __syncthreads();

    for (int i = tid; i < 80*32; i += 128) {
        int n = i >> 5, o = i & 31;
        int h = o >> 3, mm = o & 7;
        float acc = 0.f;
        #pragma unroll
        for (int e = 0; e < 8; e++) acc += X[n][h*8 + e] * kv[h][mm][e];
        O[n][o] = 0.5f * acc;
    }
    __syncthreads();

    if (tid < 80) {
        float sq = 0.f;
        #pragma unroll
        for (int c = 0; c < 32; c++) { float q = O[tid][c]; sq += q*q; }
        float nrm = fminf(fmaxf(sqrtf(sq), 1e-10f), 1.0f - 1e-5f);
        float sc = atanhf(-nrm) / nrm;
        size_t base = (size_t)toks[tid]*CDIM + 128 + mode*32;
        #pragma unroll
        for (int c = 0; c < 32; c++) g_cat[base + c] = O[tid][c] * sc;
    }
}

// ---------------- final transpose ----------------
__global__ __launch_bounds__(256) void k_out(float* __restrict__ out) {
    int blk = blockIdx.x;
    int vh = blk & 1;
    int bt = blk >> 1;
    int bb = bt / TDIM, t = bt % TDIM;
    __shared__ float s[25][257];
    int tid = threadIdx.x;
    size_t tok0 = (size_t)bt*VDIM + vh*25;
    for (int i = tid; i < 25*CDIM; i += 256) {
        int v = i >> 8, c = i & 255;
        s[v][c] = g_out2[(tok0 + v)*CDIM + c];
    }
    __syncthreads();
    for (int i = tid; i < 25*CDIM; i += 256) {
        int c = i / 25, v = i % 25;
        out[(((size_t)bb*CDIM + c)*TDIM + t)*VDIM + vh*25 + v] = s[v][c];
    }
}

// ---------------- launch ----------------
extern "C" void kernel_launch(void* const* d_in, const int* in_sizes, int n_in,
                              void* d_out, int out_size) {
    const float* x       = (const float*)d_in[0];
    const float* n1w     = (const float*)d_in[1];
    const float* n1b     = (const float*)d_in[2];
    const float* map_w   = (const float*)d_in[3];
    const float* map_b   = (const float*)d_in[4];
    const float* gconv   = (const float*)d_in[5];
    const float* tconv_w = (const float*)d_in[6];
    const float* tconv_b = (const float*)d_in[7];
    const float* proj_w  = (const float*)d_in[8];
    const float* proj_b  = (const float*)d_in[9];
    const float* n2w     = (const float*)d_in[10];
    const float* n2b     = (const float*)d_in[11];
    const float* mlp_w1  = (const float*)d_in[12];
    const float* mlp_b1  = (const float*)d_in[13];
    const float* mlp_w2  = (const float*)d_in[14];
    const float* mlp_b2  = (const float*)d_in[15];
    float* out = (float*)d_out;

    float *p_xt, *p_xln, *p_f, *p_cat, *p_out1, *p_ln2, *p_h, *p_out2;
    cudaGetSymbolAddress((void**)&p_xt,   g_xt);
    cudaGetSymbolAddress((void**)&p_xln,  g_xln);
    cudaGetSymbolAddress((void**)&p_f,    g_f);
    cudaGetSymbolAddress((void**)&p_cat,  g_cat);
    cudaGetSymbolAddress((void**)&p_out1, g_out1);
    cudaGetSymbolAddress((void**)&p_ln2,  g_ln2);
    cudaGetSymbolAddress((void**)&p_h,    g_h);
    cudaGetSymbolAddress((void**)&p_out2, g_out2);

    k_trans<<<dim3(BDIM*TDIM, 4), 256>>>(x);
    k_ln<<<TOK, 256>>>(p_xt, p_xln, n1w, n1b);
    k_gemm_tc<0><<<dim3(C2/128, TOK/128), 256>>>(p_xln, map_w, map_b, nullptr, p_f, TOK, C2, CDIM);
    k_gconv<<<BDIM*TDIM, 256>>>(gconv);
    k_tconv<<<BDIM*TDIM, 256>>>(tconv_w, tconv_b);
    k_attn<<<4*BDIM*40, 128>>>();
    k_gemm_tc<1><<<dim3(CDIM/128, TOK/128), 256>>>(p_cat, proj_w, proj_b, p_xt, p_out1, TOK, CDIM, CDIM);
    k_ln<<<TOK, 256>>>(p_out1, p_ln2, n2w, n2b);
    k_gemm_tc<2><<<dim3(C4/128, TOK/128), 256>>>(p_ln2, mlp_w1, mlp_b1, nullptr, p_h, TOK, C4, CDIM);
    k_gemm_tc<1><<<dim3(CDIM/128, TOK/128), 256>>>(p_h, mlp_w2, mlp_b2, p_out1, p_out2, TOK, CDIM, C4);
    k_out<<<BDIM*TDIM*2, 256>>>(out);
}

// round 4
// speedup vs baseline: 2.9260x; 1.6851x over previous
#include <cuda_runtime.h>
#include <cuda_fp16.h>
#include <math.h>

#define BDIM 32
#define CDIM 256
#define TDIM 64
#define VDIM 50
#define TOK (BDIM*TDIM*VDIM)   // 102400
#define C2  512
#define C4  1024

// ---------------- scratch ----------------
__device__ float  g_xt  [TOK*CDIM];   // skip (fp32)
__device__ float  g_f   [TOK*C2];     // map output (fp32, read by branches)
__device__ float  g_out1[TOK*CDIM];   // proj + skip (fp32)
__device__ float  g_out2[TOK*CDIM];   // final token-major (fp32)
__device__ __half h_xln [TOK*CDIM];   // LN1 out (GEMM A)
__device__ __half h_cat [TOK*CDIM];   // branch concat (GEMM A)
__device__ __half h_ln2 [TOK*CDIM];   // LN2 out (GEMM A)
__device__ __half h_h   [TOK*C4];     // mlp hidden (GEMM A)
__device__ __half2 w_map [(CDIM/2)*C2];
__device__ __half2 w_proj[(CDIM/2)*CDIM];
__device__ __half2 w_m1  [(CDIM/2)*C4];
__device__ __half2 w_m2  [(C4/2)*CDIM];

__device__ __forceinline__ unsigned sptr(const void* p) {
    return (unsigned)__cvta_generic_to_shared(p);
}
__device__ __forceinline__ void cpa16(unsigned d, const void* s) {
    asm volatile("cp.async.cg.shared.global [%0], [%1], 16;\n" :: "r"(d), "l"(s));
}

// ---------------- weight convert + k-pair interleave ----------------
// out[k2*N + n] = (w[2k2][n], w[2k2+1][n])
__global__ __launch_bounds__(256) void k_wpair(const float* __restrict__ w,
                                               __half2* __restrict__ o,
                                               int K, int N) {
    int idx = blockIdx.x*256 + threadIdx.x;
    int total = (K/2)*N;
    if (idx >= total) return;
    int k2 = idx / N, n = idx - k2*N;
    o[idx] = __floats2half2_rn(w[(size_t)(2*k2)*N + n], w[(size_t)(2*k2+1)*N + n]);
}

// ---------------- transpose x (B,C,T,V) -> token-major fp32 ----------------
__global__ __launch_bounds__(256) void k_trans(const float* __restrict__ x) {
    int bt = blockIdx.x;
    int cc = blockIdx.y;
    int bb = bt / TDIM, t = bt % TDIM;
    __shared__ float s[64][51];
    int tid = threadIdx.x;
    const float* xp = x + ((size_t)bb*CDIM + cc*64)*(TDIM*VDIM) + (size_t)t*VDIM;
    for (int i = tid; i < 64*VDIM; i += 256) {
        int c = i / VDIM, v = i % VDIM;
        s[c][v] = xp[(size_t)c*TDIM*VDIM + v];
    }
    __syncthreads();
    size_t tok0 = (size_t)bt*VDIM;
    for (int i = tid; i < 64*VDIM; i += 256) {
        int v = i >> 6, c = i & 63;
        g_xt[(tok0+v)*CDIM + cc*64 + c] = s[c][v];
    }
}

// ---------------- LayerNorm (fp32 in, half out) ----------------
__global__ __launch_bounds__(256) void k_ln(const float* __restrict__ src,
                                            __half* __restrict__ dst,
                                            const float* __restrict__ w,
                                            const float* __restrict__ b) {
    size_t m = blockIdx.x;
    int c = threadIdx.x;
    float q = src[m*CDIM + c];
    float s1 = q, s2 = q*q;
    #pragma unroll
    for (int o = 16; o; o >>= 1) {
        s1 += __shfl_xor_sync(0xffffffffu, s1, o);
        s2 += __shfl_xor_sync(0xffffffffu, s2, o);
    }
    __shared__ float red[18];
    int wid = c >> 5, lid = c & 31;
    if (lid == 0) { red[wid] = s1; red[8+wid] = s2; }
    __syncthreads();
    if (c == 0) {
        float a1 = 0.f, a2 = 0.f;
        for (int i = 0; i < 8; i++) { a1 += red[i]; a2 += red[8+i]; }
        float mean = a1 * (1.0f/CDIM);
        float var  = a2 * (1.0f/CDIM) - mean*mean;
        red[16] = mean;
        red[17] = rsqrtf(var + 1e-5f);
    }
    __syncthreads();
    dst[m*CDIM + c] = __float2half((q - red[16]) * red[17] * w[c] + b[c]);
}

// ---------------- fp16 tensor-core GEMM 128x128x32, cp.async 2-stage ----------------
// EPI: 0 = bias -> fp32 C, 1 = bias + extra(fp32) -> fp32 C, 2 = bias + gelu -> half C
#define SA 40    // As stride (halves)
#define SB 136   // Bs stride (half2)
template<int EPI>
__global__ __launch_bounds__(256, 2) void k_gemm_h(const __half* __restrict__ A,
                                                   const __half2* __restrict__ Bp,
                                                   const float* __restrict__ bias,
                                                   const float* __restrict__ extra,
                                                   void* __restrict__ Cout,
                                                   int M, int N, int K) {
    __shared__ __align__(16) __half  As[2][128*SA];
    __shared__ __align__(16) __half2 Bs[2][16*SB];
    int tid = threadIdx.x, lane = tid & 31, warp = tid >> 5;
    int wm = warp >> 2, wn = warp & 3;
    int m0 = blockIdx.y * 128, n0 = blockIdx.x * 128;
    int r = lane >> 2, c = lane & 3;

    float acc[4][4][4];
    #pragma unroll
    for (int i = 0; i < 4; i++)
        #pragma unroll
        for (int j = 0; j < 4; j++)
            #pragma unroll
            for (int q = 0; q < 4; q++) acc[i][j][q] = 0.f;

    auto stage = [&](int s, int k0) {
        #pragma unroll
        for (int hh = 0; hh < 2; hh++) {
            int ch = tid + hh*256;                 // A: 512 chunks, 128 rows x 4
            int row = ch >> 2, seg = ch & 3;
            cpa16(sptr(&As[s][row*SA + seg*8]),
                  A + (size_t)(m0+row)*K + k0 + seg*8);
        }
        int k20 = k0 >> 1;
        #pragma unroll
        for (int hh = 0; hh < 2; hh++) {
            int ch = tid + hh*256;                 // B: 512 chunks, 16 rows x 32
            int k2 = ch >> 5, seg = ch & 31;
            cpa16(sptr(&Bs[s][k2*SB + seg*4]),
                  Bp + (size_t)(k20+k2)*N + n0 + seg*4);
        }
    };

    int nt = K >> 5;
    stage(0, 0);
    asm volatile("cp.async.commit_group;\n");

    // precomputed ldmatrix lane offset (bytes within As)
    int lrow = (lane & 7) + ((lane >> 3) & 1)*8;
    int lcol = ((lane >> 4) & 1)*8;

    for (int t = 0; t < nt; t++) {
        if (t+1 < nt) {
            stage((t+1) & 1, (t+1)*32);
            asm volatile("cp.async.commit_group;\n");
            asm volatile("cp.async.wait_group 1;\n");
        } else {
            asm volatile("cp.async.wait_group 0;\n");
        }
        __syncthreads();
        int s = t & 1;
        #pragma unroll
        for (int kk = 0; kk < 32; kk += 16) {
            unsigned af[4][4];
            #pragma unroll
            for (int i = 0; i < 4; i++) {
                int row = wm*64 + i*16 + lrow;
                unsigned ad = sptr(&As[s][row*SA + kk + lcol]);
                asm volatile("ldmatrix.sync.aligned.m8n8.x4.shared.b16 {%0,%1,%2,%3}, [%4];"
                    : "=r"(af[i][0]), "=r"(af[i][1]), "=r"(af[i][2]), "=r"(af[i][3])
                    : "r"(ad));
            }
            int kk2 = kk >> 1;
            unsigned bf[4][2];
            #pragma unroll
            for (int j = 0; j < 4; j++) {
                int nb = wn*32 + j*8 + r;
                bf[j][0] = *(const unsigned*)&Bs[s][(kk2+c  )*SB + nb];
                bf[j][1] = *(const unsigned*)&Bs[s][(kk2+c+4)*SB + nb];
            }
            #pragma unroll
            for (int i = 0; i < 4; i++)
                #pragma unroll
                for (int j = 0; j < 4; j++) {
                    asm volatile(
                        "mma.sync.aligned.m16n8k16.row.col.f32.f16.f16.f32 "
                        "{%0,%1,%2,%3}, {%4,%5,%6,%7}, {%8,%9}, {%0,%1,%2,%3};"
                        : "+f"(acc[i][j][0]), "+f"(acc[i][j][1]),
                          "+f"(acc[i][j][2]), "+f"(acc[i][j][3])
                        : "r"(af[i][0]), "r"(af[i][1]), "r"(af[i][2]), "r"(af[i][3]),
                          "r"(bf[j][0]), "r"(bf[j][1]));
                }
        }
        __syncthreads();
    }

    #pragma unroll
    for (int i = 0; i < 4; i++) {
        #pragma unroll
        for (int j = 0; j < 4; j++) {
            int row0 = m0 + wm*64 + i*16 + r;
            int col  = n0 + wn*32 + j*8 + c*2;
            float b0 = bias[col], b1 = bias[col+1];
            #pragma unroll
            for (int hh = 0; hh < 2; hh++) {
                size_t mrow = (size_t)(row0 + hh*8);
                float v0 = acc[i][j][2*hh+0] + b0;
                float v1 = acc[i][j][2*hh+1] + b1;
                if (EPI == 1) {
                    const float2 e = *(const float2*)&extra[mrow*N + col];
                    v0 += e.x; v1 += e.y;
                }
                if (EPI == 2) {
                    v0 = 0.5f * v0 * (1.0f + erff(v0 * 0.70710678118654752f));
                    v1 = 0.5f * v1 * (1.0f + erff(v1 * 0.70710678118654752f));
                    *(__half2*)((__half*)Cout + mrow*N + col) = __floats2half2_rn(v0, v1);
                } else {
                    float2 o; o.x = v0; o.y = v1;
                    *(float2*)((float*)Cout + mrow*N + col) = o;
                }
            }
        }
    }
}

// ---------------- gconv branch: channels 0..63 ----------------
__global__ __launch_bounds__(256) void k_gconv(const float* __restrict__ gw) {
    int bt = blockIdx.x;
    __shared__ float fg[VDIM][64];
    int tid = threadIdx.x;
    size_t tok0 = (size_t)bt * VDIM;
    for (int i = tid; i < VDIM*16; i += 256) {
        int u = i >> 4, q = i & 15;
        *(float4*)&fg[u][q*4] = *(const float4*)&g_f[(tok0+u)*C2 + q*4];
    }
    __syncthreads();
    for (int i = tid; i < VDIM*8; i += 256) {
        int v = i >> 3, g = i & 7;
        const float* gwp = gw + ((size_t)g*VDIM + v)*VDIM;
        float acc[8];
        #pragma unroll
        for (int o = 0; o < 8; o++) acc[o] = 0.f;
        #pragma unroll 10
        for (int u = 0; u < VDIM; u++) {
            float wv = gwp[u];
            #pragma unroll
            for (int o = 0; o < 8; o++) acc[o] += wv * fg[u][g*8 + o];
        }
        __half* dst = h_cat + (tok0+v)*CDIM + g*8;
        #pragma unroll
        for (int o = 0; o < 8; o += 2)
            *(__half2*)&dst[o] = __floats2half2_rn(acc[o], acc[o+1]);
    }
}

// ---------------- grouped temporal conv: channels 64..127 ----------------
__global__ __launch_bounds__(256) void k_tconv(const float* __restrict__ w,
                                               const float* __restrict__ bias) {
    int bt = blockIdx.x;
    int bb = bt / TDIM, t = bt % TDIM;
    __shared__ float ws[56*64];     // [ic*7+dt][o]
    int tid = threadIdx.x;
    for (int i = tid; i < 64*56; i += 256) {
        int o = i / 56, rr = i % 56;
        ws[rr*64 + o] = w[i];
    }
    __syncthreads();
    size_t tok0 = (size_t)bt * VDIM;
    for (int i = tid; i < VDIM*8; i += 256) {
        int v = i >> 3, g = i & 7;
        float acc[8];
        #pragma unroll
        for (int o = 0; o < 8; o++) acc[o] = bias[g*8 + o];
        #pragma unroll
        for (int dt = 0; dt < 7; dt++) {
            int tt = t + dt - 3;
            if (tt < 0 || tt >= TDIM) continue;
            const float* xp = &g_f[((size_t)(bb*TDIM + tt)*VDIM + v)*C2 + 64 + g*8];
            float4 x0 = *(const float4*)xp;
            float4 x1 = *(const float4*)(xp + 4);
            float xv[8] = {x0.x, x0.y, x0.z, x0.w, x1.x, x1.y, x1.z, x1.w};
            #pragma unroll
            for (int ic = 0; ic < 8; ic++) {
                const float* wrow = &ws[(ic*7 + dt)*64 + g*8];
                #pragma unroll
                for (int o = 0; o < 8; o++) acc[o] += xv[ic] * wrow[o];
            }
        }
        __half* dst = h_cat + (tok0+v)*CDIM + 64 + g*8;
        #pragma unroll
        for (int o = 0; o < 8; o += 2)
            *(__half2*)&dst[o] = __floats2half2_rn(acc[o], acc[o+1]);
    }
}

// ---------------- windowed hyperbolic linear attention: channels 128..255 ----------------
__global__ __launch_bounds__(128) void k_attn() {
    int wb = blockIdx.x;
    int mode = wb / (BDIM*40);
    int rem  = wb % (BDIM*40);
    int bb = rem / 40;
    int wwin = rem % 40;
    int i0 = wwin / 5, i1 = wwin % 5;

    __shared__ float X[80][97];
    __shared__ float kv[4][8][8];
    __shared__ float O[80][33];
    __shared__ int   toks[80];
    int tid = threadIdx.x;

    if (tid < 80) {
        int a = tid / 10, e = tid % 10;
        int t, v;
        if      (mode == 0) { t = i0*8 + a; v = i1*10 + e; }
        else if (mode == 1) { t = i0*8 + a; v = e*5 + i1;  }
        else if (mode == 2) { t = a*8 + i0; v = i1*10 + e; }
        else                { t = a*8 + i0; v = e*5 + i1;  }
        toks[tid] = (bb*TDIM + t)*VDIM + v;
    }
    __syncthreads();

    int cb = 128 + mode*96;
    for (int i = tid; i < 80*96; i += 128) {
        int n = i / 96, c = i % 96;
        X[n][c] = g_f[(size_t)toks[n]*C2 + cb + c];
    }
    __syncthreads();

    if (tid < 80) {
        float sq = 0.f;
        #pragma unroll 8
        for (int c = 0; c < 96; c++) { float q = X[tid][c]; sq += q*q; }
        float nrm = fmaxf(sqrtf(sq), 1e-10f);
        float sc = tanhf(nrm) / nrm;
        #pragma unroll 8
        for (int c = 0; c < 96; c++) X[tid][c] *= sc;
    }
    __syncthreads();

    for (int i = tid; i < 256; i += 128) {
        int h = i >> 6, d = (i >> 3) & 7, e = i & 7;
        float acc = 0.f;
        for (int n = 0; n < 80; n++)
            acc += X[n][32 + h*8 + d] * X[n][64 + h*8 + e];
        kv[h][d][e] = acc;
    }
    __syncthreads();

    if (tid < 32) {
        int h = tid >> 3, d = tid & 7;
        float mx = -1e30f;
        #pragma unroll
        for (int e = 0; e < 8; e++) mx = fmaxf(mx, kv[h][d][e]);
        float s = 0.f;
        #pragma unroll
        for (int e = 0; e < 8; e++) { float q = expf(kv[h][d][e] - mx); s += q; kv[h][d][e] = q; }
        float inv = 1.0f / s;
        #pragma unroll
        for (int e = 0; e < 8; e++) kv[h][d][e] *= inv;
    }
    __syncthreads();

    for (int i = tid; i < 80*32; i += 128) {
        int n = i >> 5, o = i & 31;
        int h = o >> 3, mm = o & 7;
        float acc = 0.f;
        #pragma unroll
        for (int e = 0; e < 8; e++) acc += X[n][h*8 + e] * kv[h][mm][e];
        O[n][o] = 0.5f * acc;
    }
    __syncthreads();

    if (tid < 80) {
        float sq = 0.f;
        #pragma unroll
        for (int c = 0; c < 32; c++) { float q = O[tid][c]; sq += q*q; }
        float nrm = fminf(fmaxf(sqrtf(sq), 1e-10f), 1.0f - 1e-5f);
        float sc = atanhf(-nrm) / nrm;
        __half* dst = h_cat + (size_t)toks[tid]*CDIM + 128 + mode*32;
        #pragma unroll
        for (int c = 0; c < 32; c++) dst[c] = __float2half(O[tid][c] * sc);
    }
}

// ---------------- final transpose ----------------
__global__ __launch_bounds__(256) void k_out(float* __restrict__ out) {
    int blk = blockIdx.x;
    int vh = blk & 1;
    int bt = blk >> 1;
    int bb = bt / TDIM, t = bt % TDIM;
    __shared__ float s[25][257];
    int tid = threadIdx.x;
    size_t tok0 = (size_t)bt*VDIM + vh*25;
    for (int i = tid; i < 25*CDIM; i += 256) {
        int v = i >> 8, c = i & 255;
        s[v][c] = g_out2[(tok0 + v)*CDIM + c];
    }
    __syncthreads();
    for (int i = tid; i < 25*CDIM; i += 256) {
        int c = i / 25, v = i % 25;
        out[(((size_t)bb*CDIM + c)*TDIM + t)*VDIM + vh*25 + v] = s[v][c];
    }
}

// ---------------- launch ----------------
extern "C" void kernel_launch(void* const* d_in, const int* in_sizes, int n_in,
                              void* d_out, int out_size) {
    const float* x       = (const float*)d_in[0];
    const float* n1w     = (const float*)d_in[1];
    const float* n1b     = (const float*)d_in[2];
    const float* map_w   = (const float*)d_in[3];
    const float* map_b   = (const float*)d_in[4];
    const float* gconv   = (const float*)d_in[5];
    const float* tconv_w = (const float*)d_in[6];
    const float* tconv_b = (const float*)d_in[7];
    const float* proj_w  = (const float*)d_in[8];
    const float* proj_b  = (const float*)d_in[9];
    const float* n2w     = (const float*)d_in[10];
    const float* n2b     = (const float*)d_in[11];
    const float* mlp_w1  = (const float*)d_in[12];
    const float* mlp_b1  = (const float*)d_in[13];
    const float* mlp_w2  = (const float*)d_in[14];
    const float* mlp_b2  = (const float*)d_in[15];
    float* out = (float*)d_out;

    float *p_xt, *p_f, *p_out1, *p_out2;
    __half *p_xln, *p_cat, *p_ln2, *p_h;
    __half2 *p_wmap, *p_wproj, *p_wm1, *p_wm2;
    cudaGetSymbolAddress((void**)&p_xt,   g_xt);
    cudaGetSymbolAddress((void**)&p_f,    g_f);
    cudaGetSymbolAddress((void**)&p_out1, g_out1);
    cudaGetSymbolAddress((void**)&p_out2, g_out2);
    cudaGetSymbolAddress((void**)&p_xln,  h_xln);
    cudaGetSymbolAddress((void**)&p_cat,  h_cat);
    cudaGetSymbolAddress((void**)&p_ln2,  h_ln2);
    cudaGetSymbolAddress((void**)&p_h,    h_h);
    cudaGetSymbolAddress((void**)&p_wmap,  w_map);
    cudaGetSymbolAddress((void**)&p_wproj, w_proj);
    cudaGetSymbolAddress((void**)&p_wm1,   w_m1);
    cudaGetSymbolAddress((void**)&p_wm2,   w_m2);

    // weight convert + pair-interleave
    k_wpair<<<(CDIM/2*C2  + 255)/256, 256>>>(map_w,  p_wmap,  CDIM, C2);
    k_wpair<<<(CDIM/2*CDIM+ 255)/256, 256>>>(proj_w, p_wproj, CDIM, CDIM);
    k_wpair<<<(CDIM/2*C4  + 255)/256, 256>>>(mlp_w1, p_wm1,   CDIM, C4);
    k_wpair<<<(C4/2*CDIM  + 255)/256, 256>>>(mlp_w2, p_wm2,   C4,   CDIM);

    k_trans<<<dim3(BDIM*TDIM, 4), 256>>>(x);
    k_ln<<<TOK, 256>>>(p_xt, p_xln, n1w, n1b);
    k_gemm_h<0><<<dim3(C2/128, TOK/128), 256>>>(p_xln, p_wmap, map_b, nullptr, p_f, TOK, C2, CDIM);
    k_gconv<<<BDIM*TDIM, 256>>>(gconv);
    k_tconv<<<BDIM*TDIM, 256>>>(tconv_w, tconv_b);
    k_attn<<<4*BDIM*40, 128>>>();
    k_gemm_h<1><<<dim3(CDIM/128, TOK/128), 256>>>(p_cat, p_wproj, proj_b, p_xt, p_out1, TOK, CDIM, CDIM);
    k_ln<<<TOK, 256>>>(p_out1, p_ln2, n2w, n2b);
    k_gemm_h<2><<<dim3(C4/128, TOK/128), 256>>>(p_ln2, p_wm1, mlp_b1, nullptr, p_h, TOK, C4, CDIM);
    k_gemm_h<1><<<dim3(CDIM/128, TOK/128), 256>>>(p_h, p_wm2, mlp_b2, p_out1, p_out2, TOK, CDIM, C4);
    k_out<<<BDIM*TDIM*2, 256>>>(out);
}

// round 6
// speedup vs baseline: 3.1652x; 1.0818x over previous
#include <cuda_runtime.h>
#include <cuda_fp16.h>
#include <math.h>

#define BDIM 32
#define CDIM 256
#define TDIM 64
#define VDIM 50
#define TOK (BDIM*TDIM*VDIM)   // 102400
#define C2  512
#define C4  1024

// ---------------- scratch ----------------
__device__ float  g_xt  [TOK*CDIM];   // skip (fp32)
__device__ float  g_f   [TOK*C2];     // map output (fp32)
__device__ float  g_out1[TOK*CDIM];   // proj + skip (fp32)
__device__ float  g_out2[TOK*CDIM];   // final token-major (fp32)
__device__ __half h_xln [TOK*CDIM];
__device__ __half h_cat [TOK*CDIM];
__device__ __half h_ln2 [TOK*CDIM];
__device__ __half h_h   [TOK*C4];
__device__ __half2 w_map [(CDIM/2)*C2];
__device__ __half2 w_proj[(CDIM/2)*CDIM];
__device__ __half2 w_m1  [(CDIM/2)*C4];
__device__ __half2 w_m2  [(C4/2)*CDIM];

__device__ __forceinline__ unsigned sptr(const void* p) {
    return (unsigned)__cvta_generic_to_shared(p);
}
__device__ __forceinline__ void cpa16(unsigned d, const void* s) {
    asm volatile("cp.async.cg.shared.global [%0], [%1], 16;\n" :: "r"(d), "l"(s));
}

// ---------------- weight convert + k-pair interleave ----------------
__global__ __launch_bounds__(256) void k_wpair(const float* __restrict__ w,
                                               __half2* __restrict__ o,
                                               int K, int N) {
    int idx = blockIdx.x*256 + threadIdx.x;
    int total = (K/2)*N;
    if (idx >= total) return;
    int k2 = idx / N, n = idx - k2*N;
    o[idx] = __floats2half2_rn(w[(size_t)(2*k2)*N + n], w[(size_t)(2*k2+1)*N + n]);
}

// ---------------- fused transpose + LN1: x (B,C,T,V) -> g_xt fp32 + h_xln half ----------------
__global__ __launch_bounds__(256) void k_transln(const float* __restrict__ x,
                                                 const float* __restrict__ w,
                                                 const float* __restrict__ b) {
    int bt = blockIdx.x;                 // B*T
    int bb = bt / TDIM, t = bt % TDIM;
    __shared__ float s[CDIM][51];        // [c][v]
    int tid = threadIdx.x, lane = tid & 31, warp = tid >> 5;
    const float* xp = x + (size_t)bb*CDIM*(TDIM*VDIM) + (size_t)t*VDIM;
    for (int i = tid; i < CDIM*VDIM; i += 256) {
        int c = i / VDIM, v = i - c*VDIM;
        s[c][v] = xp[(size_t)c*TDIM*VDIM + v];
    }
    __syncthreads();
    size_t tok0 = (size_t)bt*VDIM;
    for (int v = warp; v < VDIM; v += 8) {
        float q[8], s1 = 0.f, s2 = 0.f;
        #pragma unroll
        for (int i = 0; i < 8; i++) {
            q[i] = s[lane + 32*i][v];
            s1 += q[i]; s2 += q[i]*q[i];
        }
        #pragma unroll
        for (int o = 16; o; o >>= 1) {
            s1 += __shfl_xor_sync(0xffffffffu, s1, o);
            s2 += __shfl_xor_sync(0xffffffffu, s2, o);
        }
        float mean = s1 * (1.0f/CDIM);
        float var  = s2 * (1.0f/CDIM) - mean*mean;
        float rstd = rsqrtf(var + 1e-5f);
        size_t base = (tok0 + v)*CDIM;
        #pragma unroll
        for (int i = 0; i < 8; i++) {
            int c = lane + 32*i;
            g_xt[base + c] = q[i];
            h_xln[base + c] = __float2half((q[i] - mean) * rstd * w[c] + b[c]);
        }
    }
}

// ---------------- LayerNorm (fp32 in, half out) ----------------
__global__ __launch_bounds__(256) void k_ln(const float* __restrict__ src,
                                            __half* __restrict__ dst,
                                            const float* __restrict__ w,
                                            const float* __restrict__ b) {
    size_t m = blockIdx.x;
    int c = threadIdx.x;
    float q = src[m*CDIM + c];
    float s1 = q, s2 = q*q;
    #pragma unroll
    for (int o = 16; o; o >>= 1) {
        s1 += __shfl_xor_sync(0xffffffffu, s1, o);
        s2 += __shfl_xor_sync(0xffffffffu, s2, o);
    }
    __shared__ float red[18];
    int wid = c >> 5, lid = c & 31;
    if (lid == 0) { red[wid] = s1; red[8+wid] = s2; }
    __syncthreads();
    if (c == 0) {
        float a1 = 0.f, a2 = 0.f;
        for (int i = 0; i < 8; i++) { a1 += red[i]; a2 += red[8+i]; }
        float mean = a1 * (1.0f/CDIM);
        float var  = a2 * (1.0f/CDIM) - mean*mean;
        red[16] = mean;
        red[17] = rsqrtf(var + 1e-5f);
    }
    __syncthreads();
    dst[m*CDIM + c] = __float2half((q - red[16]) * red[17] * w[c] + b[c]);
}

// ---------------- fp16 tensor-core GEMM 128x128x32, cp.async 3-stage ----------------
// EPI: 0 = bias -> fp32, 1 = bias + extra(fp32) -> fp32, 2 = bias + gelu -> half
#define SA 40    // As stride (halves)
#define SB 136   // Bs stride (half2)
template<int EPI>
__global__ __launch_bounds__(256, 2) void k_gemm_h(const __half* __restrict__ A,
                                                   const __half2* __restrict__ Bp,
                                                   const float* __restrict__ bias,
                                                   const float* __restrict__ extra,
                                                   void* __restrict__ Cout,
                                                   int M, int N, int K) {
    __shared__ __align__(16) __half  As[3][128*SA];
    __shared__ __align__(16) __half2 Bs[3][16*SB];
    int tid = threadIdx.x, lane = tid & 31, warp = tid >> 5;
    int wm = warp >> 2, wn = warp & 3;
    int m0 = blockIdx.y * 128, n0 = blockIdx.x * 128;
    int r = lane >> 2, c = lane & 3;

    float acc[4][4][4];
    #pragma unroll
    for (int i = 0; i < 4; i++)
        #pragma unroll
        for (int j = 0; j < 4; j++)
            #pragma unroll
            for (int q = 0; q < 4; q++) acc[i][j][q] = 0.f;

    auto stage = [&](int s, int k0) {
        #pragma unroll
        for (int hh = 0; hh < 2; hh++) {
            int ch = tid + hh*256;                 // A: 512 chunks, 128 rows x 4
            int row = ch >> 2, seg = ch & 3;
            cpa16(sptr(&As[s][row*SA + seg*8]),
                  A + (size_t)(m0+row)*K + k0 + seg*8);
        }
        int k20 = k0 >> 1;
        #pragma unroll
        for (int hh = 0; hh < 2; hh++) {
            int ch = tid + hh*256;                 // B: 512 chunks, 16 rows x 32
            int k2 = ch >> 5, seg = ch & 31;
            cpa16(sptr(&Bs[s][k2*SB + seg*4]),
                  Bp + (size_t)(k20+k2)*N + n0 + seg*4);
        }
    };

    int nt = K >> 5;
    stage(0, 0);
    asm volatile("cp.async.commit_group;\n");
    stage(1, 32);
    asm volatile("cp.async.commit_group;\n");

    int lrow = (lane & 7) + ((lane >> 3) & 1)*8;
    int lcol = ((lane >> 4) & 1)*8;

    for (int t = 0; t < nt; t++) {
        if (t+1 < nt) asm volatile("cp.async.wait_group 1;\n");
        else          asm volatile("cp.async.wait_group 0;\n");
        __syncthreads();
        int s = t % 3;
        #pragma unroll
        for (int kk = 0; kk < 32; kk += 16) {
            unsigned af[4][4];
            #pragma unroll
            for (int i = 0; i < 4; i++) {
                int row = wm*64 + i*16 + lrow;
                unsigned ad = sptr(&As[s][row*SA + kk + lcol]);
                asm volatile("ldmatrix.sync.aligned.m8n8.x4.shared.b16 {%0,%1,%2,%3}, [%4];"
                    : "=r"(af[i][0]), "=r"(af[i][1]), "=r"(af[i][2]), "=r"(af[i][3])
                    : "r"(ad));
            }
            int kk2 = kk >> 1;
            unsigned bf[4][2];
            #pragma unroll
            for (int j = 0; j < 4; j++) {
                int nb = wn*32 + j*8 + r;
                bf[j][0] = *(const unsigned*)&Bs[s][(kk2+c  )*SB + nb];
                bf[j][1] = *(const unsigned*)&Bs[s][(kk2+c+4)*SB + nb];
            }
            #pragma unroll
            for (int i = 0; i < 4; i++)
                #pragma unroll
                for (int j = 0; j < 4; j++) {
                    asm volatile(
                        "mma.sync.aligned.m16n8k16.row.col.f32.f16.f16.f32 "
                        "{%0,%1,%2,%3}, {%4,%5,%6,%7}, {%8,%9}, {%0,%1,%2,%3};"
                        : "+f"(acc[i][j][0]), "+f"(acc[i][j][1]),
                          "+f"(acc[i][j][2]), "+f"(acc[i][j][3])
                        : "r"(af[i][0]), "r"(af[i][1]), "r"(af[i][2]), "r"(af[i][3]),
                          "r"(bf[j][0]), "r"(bf[j][1]));
                }
        }
        if (t+2 < nt) {
            stage((t+2) % 3, (t+2)*32);
            asm volatile("cp.async.commit_group;\n");
        }
    }

    #pragma unroll
    for (int i = 0; i < 4; i++) {
        #pragma unroll
        for (int j = 0; j < 4; j++) {
            int row0 = m0 + wm*64 + i*16 + r;
            int col  = n0 + wn*32 + j*8 + c*2;
            float b0 = bias[col], b1 = bias[col+1];
            #pragma unroll
            for (int hh = 0; hh < 2; hh++) {
                size_t mrow = (size_t)(row0 + hh*8);
                float v0 = acc[i][j][2*hh+0] + b0;
                float v1 = acc[i][j][2*hh+1] + b1;
                if (EPI == 1) {
                    const float2 e = *(const float2*)&extra[mrow*N + col];
                    v0 += e.x; v1 += e.y;
                }
                if (EPI == 2) {
                    v0 = 0.5f * v0 * (1.0f + erff(v0 * 0.70710678118654752f));
                    v1 = 0.5f * v1 * (1.0f + erff(v1 * 0.70710678118654752f));
                    *(__half2*)((__half*)Cout + mrow*N + col) = __floats2half2_rn(v0, v1);
                } else {
                    float2 o; o.x = v0; o.y = v1;
                    *(float2*)((float*)Cout + mrow*N + col) = o;
                }
            }
        }
    }
}

// ---------------- gconv branch: channels 0..63 ----------------
__global__ __launch_bounds__(256) void k_gconv(const float* __restrict__ gw) {
    int bt = blockIdx.x;
    __shared__ float fg[VDIM][64];
    int tid = threadIdx.x;
    size_t tok0 = (size_t)bt * VDIM;
    for (int i = tid; i < VDIM*16; i += 256) {
        int u = i >> 4, q = i & 15;
        *(float4*)&fg[u][q*4] = *(const float4*)&g_f[(tok0+u)*C2 + q*4];
    }
    __syncthreads();
    for (int i = tid; i < VDIM*8; i += 256) {
        int v = i >> 3, g = i & 7;
        const float* gwp = gw + ((size_t)g*VDIM + v)*VDIM;
        float acc[8];
        #pragma unroll
        for (int o = 0; o < 8; o++) acc[o] = 0.f;
        #pragma unroll 5
        for (int u2 = 0; u2 < VDIM/2; u2++) {
            float2 wv = *(const float2*)&gwp[u2*2];
            float4 a0 = *(const float4*)&fg[2*u2][g*8];
            float4 a1 = *(const float4*)&fg[2*u2][g*8+4];
            float4 b0 = *(const float4*)&fg[2*u2+1][g*8];
            float4 b1 = *(const float4*)&fg[2*u2+1][g*8+4];
            acc[0] += wv.x*a0.x + wv.y*b0.x;
            acc[1] += wv.x*a0.y + wv.y*b0.y;
            acc[2] += wv.x*a0.z + wv.y*b0.z;
            acc[3] += wv.x*a0.w + wv.y*b0.w;
            acc[4] += wv.x*a1.x + wv.y*b1.x;
            acc[5] += wv.x*a1.y + wv.y*b1.y;
            acc[6] += wv.x*a1.z + wv.y*b1.z;
            acc[7] += wv.x*a1.w + wv.y*b1.w;
        }
        __half* dst = h_cat + (tok0+v)*CDIM + g*8;
        #pragma unroll
        for (int o = 0; o < 8; o += 2)
            *(__half2*)&dst[o] = __floats2half2_rn(acc[o], acc[o+1]);
    }
}

// ---------------- grouped temporal conv: channels 64..127 ----------------
__global__ __launch_bounds__(256) void k_tconv(const float* __restrict__ w,
                                               const float* __restrict__ bias) {
    int bt = blockIdx.x;
    int bb = bt / TDIM, t = bt % TDIM;
    __shared__ float ws[56*64];     // [ic*7+dt][o]
    int tid = threadIdx.x;
    for (int i = tid; i < 64*56; i += 256) {
        int o = i / 56, rr = i % 56;
        ws[rr*64 + o] = w[i];
    }
    __syncthreads();
    size_t tok0 = (size_t)bt * VDIM;
    for (int i = tid; i < VDIM*8; i += 256) {
        int v = i >> 3, g = i & 7;
        float acc[8];
        #pragma unroll
        for (int o = 0; o < 8; o++) acc[o] = bias[g*8 + o];
        #pragma unroll
        for (int dt = 0; dt < 7; dt++) {
            int tt = t + dt - 3;
            if (tt < 0 || tt >= TDIM) continue;
            const float* xp = &g_f[((size_t)(bb*TDIM + tt)*VDIM + v)*C2 + 64 + g*8];
            float4 x0 = *(const float4*)xp;
            float4 x1 = *(const float4*)(xp + 4);
            float xv[8] = {x0.x, x0.y, x0.z, x0.w, x1.x, x1.y, x1.z, x1.w};
            #pragma unroll
            for (int ic = 0; ic < 8; ic++) {
                float4 w0 = *(const float4*)&ws[(ic*7 + dt)*64 + g*8];
                float4 w1 = *(const float4*)&ws[(ic*7 + dt)*64 + g*8 + 4];
                acc[0] += xv[ic]*w0.x; acc[1] += xv[ic]*w0.y;
                acc[2] += xv[ic]*w0.z; acc[3] += xv[ic]*w0.w;
                acc[4] += xv[ic]*w1.x; acc[5] += xv[ic]*w1.y;
                acc[6] += xv[ic]*w1.z; acc[7] += xv[ic]*w1.w;
            }
        }
        __half* dst = h_cat + (tok0+v)*CDIM + 64 + g*8;
        #pragma unroll
        for (int o = 0; o < 8; o += 2)
            *(__half2*)&dst[o] = __floats2half2_rn(acc[o], acc[o+1]);
    }
}

// ---------------- windowed hyperbolic linear attention: channels 128..255 ----------------
__global__ __launch_bounds__(128) void k_attn() {
    int wb = blockIdx.x;
    int mode = wb / (BDIM*40);
    int rem  = wb % (BDIM*40);
    int bb = rem / 40;
    int wwin = rem % 40;
    int i0 = wwin / 5, i1 = wwin % 5;

    __shared__ float X[80][97];
    __shared__ float kv[4][8][8];
    __shared__ float O[80][33];
    __shared__ int   toks[80];
    int tid = threadIdx.x;

    if (tid < 80) {
        int a = tid / 10, e = tid % 10;
        int t, v;
        if      (mode == 0) { t = i0*8 + a; v = i1*10 + e; }
        else if (mode == 1) { t = i0*8 + a; v = e*5 + i1;  }
        else if (mode == 2) { t = a*8 + i0; v = i1*10 + e; }
        else                { t = a*8 + i0; v = e*5 + i1;  }
        toks[tid] = (bb*TDIM + t)*VDIM + v;
    }
    __syncthreads();

    int cb = 128 + mode*96;
    for (int i = tid; i < 80*96; i += 128) {
        int n = i / 96, c = i % 96;
        X[n][c] = g_f[(size_t)toks[n]*C2 + cb + c];
    }
    __syncthreads();

    if (tid < 80) {
        float sq = 0.f;
        #pragma unroll 8
        for (int c = 0; c < 96; c++) { float q = X[tid][c]; sq += q*q; }
        float nrm = fmaxf(sqrtf(sq), 1e-10f);
        float sc = tanhf(nrm) / nrm;
        #pragma unroll 8
        for (int c = 0; c < 96; c++) X[tid][c] *= sc;
    }
    __syncthreads();

    for (int i = tid; i < 256; i += 128) {
        int h = i >> 6, d = (i >> 3) & 7, e = i & 7;
        float acc = 0.f;
        for (int n = 0; n < 80; n++)
            acc += X[n][32 + h*8 + d] * X[n][64 + h*8 + e];
        kv[h][d][e] = acc;
    }
    __syncthreads();

    if (tid < 32) {
        int h = tid >> 3, d = tid & 7;
        float mx = -1e30f;
        #pragma unroll
        for (int e = 0; e < 8; e++) mx = fmaxf(mx, kv[h][d][e]);
        float s = 0.f;
        #pragma unroll
        for (int e = 0; e < 8; e++) { float q = expf(kv[h][d][e] - mx); s += q; kv[h][d][e] = q; }
        float inv = 1.0f / s;
        #pragma unroll
        for (int e = 0; e < 8; e++) kv[h][d][e] *= inv;
    }
    __syncthreads();

    for (int i = tid; i < 80*32; i += 128) {
        int n = i >> 5, o = i & 31;
        int h = o >> 3, mm = o & 7;
        float acc = 0.f;
        #pragma unroll
        for (int e = 0; e < 8; e++) acc += X[n][h*8 + e] * kv[h][mm][e];
        O[n][o] = 0.5f * acc;
    }
    __syncthreads();

    if (tid < 80) {
        float sq = 0.f;
        #pragma unroll
        for (int c = 0; c < 32; c++) { float q = O[tid][c]; sq += q*q; }
        float nrm = fminf(fmaxf(sqrtf(sq), 1e-10f), 1.0f - 1e-5f);
        float sc = atanhf(-nrm) / nrm;
        __half* dst = h_cat + (size_t)toks[tid]*CDIM + 128 + mode*32;
        #pragma unroll
        for (int c = 0; c < 32; c++) dst[c] = __float2half(O[tid][c] * sc);
    }
}

// ---------------- final transpose ----------------
__global__ __launch_bounds__(256) void k_out(float* __restrict__ out) {
    int blk = blockIdx.x;
    int vh = blk & 1;
    int bt = blk >> 1;
    int bb = bt / TDIM, t = bt % TDIM;
    __shared__ float s[25][257];
    int tid = threadIdx.x;
    size_t tok0 = (size_t)bt*VDIM + vh*25;
    for (int i = tid; i < 25*CDIM; i += 256) {
        int v = i >> 8, c = i & 255;
        s[v][c] = g_out2[(tok0 + v)*CDIM + c];
    }
    __syncthreads();
    for (int i = tid; i < 25*CDIM; i += 256) {
        int c = i / 25, v = i % 25;
        out[(((size_t)bb*CDIM + c)*TDIM + t)*VDIM + vh*25 + v] = s[v][c];
    }
}

// ---------------- launch ----------------
extern "C" void kernel_launch(void* const* d_in, const int* in_sizes, int n_in,
                              void* d_out, int out_size) {
    const float* x       = (const float*)d_in[0];
    const float* n1w     = (const float*)d_in[1];
    const float* n1b     = (const float*)d_in[2];
    const float* map_w   = (const float*)d_in[3];
    const float* map_b   = (const float*)d_in[4];
    const float* gconv   = (const float*)d_in[5];
    const float* tconv_w = (const float*)d_in[6];
    const float* tconv_b = (const float*)d_in[7];
    const float* proj_w  = (const float*)d_in[8];
    const float* proj_b  = (const float*)d_in[9];
    const float* n2w     = (const float*)d_in[10];
    const float* n2b     = (const float*)d_in[11];
    const float* mlp_w1  = (const float*)d_in[12];
    const float* mlp_b1  = (const float*)d_in[13];
    const float* mlp_w2  = (const float*)d_in[14];
    const float* mlp_b2  = (const float*)d_in[15];
    float* out = (float*)d_out;

    float *p_xt, *p_f, *p_out1, *p_out2;
    __half *p_xln, *p_cat, *p_ln2, *p_h;
    __half2 *p_wmap, *p_wproj, *p_wm1, *p_wm2;
    cudaGetSymbolAddress((void**)&p_xt,   g_xt);
    cudaGetSymbolAddress((void**)&p_f,    g_f);
    cudaGetSymbolAddress((void**)&p_out1, g_out1);
    cudaGetSymbolAddress((void**)&p_out2, g_out2);
    cudaGetSymbolAddress((void**)&p_xln,  h_xln);
    cudaGetSymbolAddress((void**)&p_cat,  h_cat);
    cudaGetSymbolAddress((void**)&p_ln2,  h_ln2);
    cudaGetSymbolAddress((void**)&p_h,    h_h);
    cudaGetSymbolAddress((void**)&p_wmap,  w_map);
    cudaGetSymbolAddress((void**)&p_wproj, w_proj);
    cudaGetSymbolAddress((void**)&p_wm1,   w_m1);
    cudaGetSymbolAddress((void**)&p_wm2,   w_m2);

    k_wpair<<<(CDIM/2*C2  + 255)/256, 256>>>(map_w,  p_wmap,  CDIM, C2);
    k_wpair<<<(CDIM/2*CDIM+ 255)/256, 256>>>(proj_w, p_wproj, CDIM, CDIM);
    k_wpair<<<(CDIM/2*C4  + 255)/256, 256>>>(mlp_w1, p_wm1,   CDIM, C4);
    k_wpair<<<(C4/2*CDIM  + 255)/256, 256>>>(mlp_w2, p_wm2,   C4,   CDIM);

    k_transln<<<BDIM*TDIM, 256>>>(x, n1w, n1b);
    k_gemm_h<0><<<dim3(C2/128, TOK/128), 256>>>(p_xln, p_wmap, map_b, nullptr, p_f, TOK, C2, CDIM);
    k_gconv<<<BDIM*TDIM, 256>>>(gconv);
    k_tconv<<<BDIM*TDIM, 256>>>(tconv_w, tconv_b);
    k_attn<<<4*BDIM*40, 128>>>();
    k_gemm_h<1><<<dim3(CDIM/128, TOK/128), 256>>>(p_cat, p_wproj, proj_b, p_xt, p_out1, TOK, CDIM, CDIM);
    k_ln<<<TOK, 256>>>(p_out1, p_ln2, n2w, n2b);
    k_gemm_h<2><<<dim3(C4/128, TOK/128), 256>>>(p_ln2, p_wm1, mlp_b1, nullptr, p_h, TOK, C4, CDIM);
    k_gemm_h<1><<<dim3(CDIM/128, TOK/128), 256>>>(p_h, p_wm2, mlp_b2, p_out1, p_out2, TOK, CDIM, C4);
    k_out<<<BDIM*TDIM*2, 256>>>(out);
}

// round 7
// speedup vs baseline: 3.3906x; 1.0712x over previous
#include <cuda_runtime.h>
#include <cuda_fp16.h>
#include <math.h>

#define BDIM 32
#define CDIM 256
#define TDIM 64
#define VDIM 50
#define TOK (BDIM*TDIM*VDIM)   // 102400
#define TV  (TDIM*VDIM)        // 3200
#define C2  512
#define C4  1024

// ---------------- scratch ----------------
__device__ float  g_xt  [TOK*CDIM];   // skip (fp32)
__device__ float  g_out1[TOK*CDIM];   // proj + skip (fp32)
__device__ __half h_f   [TOK*C2];     // map output (half)
__device__ __half h_xln [TOK*CDIM];
__device__ __half h_cat [TOK*CDIM];
__device__ __half h_ln2 [TOK*CDIM];
__device__ __half h_h   [TOK*C4];
__device__ __half2 w_map [(CDIM/2)*C2];
__device__ __half2 w_proj[(CDIM/2)*CDIM];
__device__ __half2 w_m1  [(CDIM/2)*C4];
__device__ __half2 w_m2  [(C4/2)*CDIM];

__device__ __forceinline__ unsigned sptr(const void* p) {
    return (unsigned)__cvta_generic_to_shared(p);
}
__device__ __forceinline__ void cpa16(unsigned d, const void* s) {
    asm volatile("cp.async.cg.shared.global [%0], [%1], 16;\n" :: "r"(d), "l"(s));
}

// ---------------- weight convert + k-pair interleave ----------------
__global__ __launch_bounds__(256) void k_wpair(const float* __restrict__ w,
                                               __half2* __restrict__ o,
                                               int K, int N) {
    int idx = blockIdx.x*256 + threadIdx.x;
    int total = (K/2)*N;
    if (idx >= total) return;
    int k2 = idx / N, n = idx - k2*N;
    o[idx] = __floats2half2_rn(w[(size_t)(2*k2)*N + n], w[(size_t)(2*k2+1)*N + n]);
}

// ---------------- fused transpose + LN1 ----------------
__global__ __launch_bounds__(256) void k_transln(const float* __restrict__ x,
                                                 const float* __restrict__ w,
                                                 const float* __restrict__ b) {
    int bt = blockIdx.x;                 // B*T
    int bb = bt / TDIM, t = bt % TDIM;
    __shared__ float s[CDIM][51];        // [c][v]
    int tid = threadIdx.x, lane = tid & 31, warp = tid >> 5;
    const float* xp = x + (size_t)bb*CDIM*TV + (size_t)t*VDIM;
    for (int i = tid; i < CDIM*VDIM; i += 256) {
        int c = i / VDIM, v = i - c*VDIM;
        s[c][v] = xp[(size_t)c*TV + v];
    }
    __syncthreads();
    size_t tok0 = (size_t)bt*VDIM;
    for (int v = warp; v < VDIM; v += 8) {
        float q[8], s1 = 0.f, s2 = 0.f;
        #pragma unroll
        for (int i = 0; i < 8; i++) {
            q[i] = s[lane + 32*i][v];
            s1 += q[i]; s2 += q[i]*q[i];
        }
        #pragma unroll
        for (int o = 16; o; o >>= 1) {
            s1 += __shfl_xor_sync(0xffffffffu, s1, o);
            s2 += __shfl_xor_sync(0xffffffffu, s2, o);
        }
        float mean = s1 * (1.0f/CDIM);
        float var  = s2 * (1.0f/CDIM) - mean*mean;
        float rstd = rsqrtf(var + 1e-5f);
        size_t base = (tok0 + v)*CDIM;
        #pragma unroll
        for (int i = 0; i < 8; i++) {
            int c = lane + 32*i;
            g_xt[base + c] = q[i];
            h_xln[base + c] = __float2half((q[i] - mean) * rstd * w[c] + b[c]);
        }
    }
}

// ---------------- LayerNorm (fp32 in, half out) ----------------
__global__ __launch_bounds__(256) void k_ln(const float* __restrict__ src,
                                            __half* __restrict__ dst,
                                            const float* __restrict__ w,
                                            const float* __restrict__ b) {
    size_t m = blockIdx.x;
    int c = threadIdx.x;
    float q = src[m*CDIM + c];
    float s1 = q, s2 = q*q;
    #pragma unroll
    for (int o = 16; o; o >>= 1) {
        s1 += __shfl_xor_sync(0xffffffffu, s1, o);
        s2 += __shfl_xor_sync(0xffffffffu, s2, o);
    }
    __shared__ float red[18];
    int wid = c >> 5, lid = c & 31;
    if (lid == 0) { red[wid] = s1; red[8+wid] = s2; }
    __syncthreads();
    if (c == 0) {
        float a1 = 0.f, a2 = 0.f;
        for (int i = 0; i < 8; i++) { a1 += red[i]; a2 += red[8+i]; }
        float mean = a1 * (1.0f/CDIM);
        float var  = a2 * (1.0f/CDIM) - mean*mean;
        red[16] = mean;
        red[17] = rsqrtf(var + 1e-5f);
    }
    __syncthreads();
    dst[m*CDIM + c] = __float2half((q - red[16]) * red[17] * w[c] + b[c]);
}

// ---------------- fp16 tensor-core GEMM 128x128x32, cp.async 3-stage ----------------
// EPI: 0 bias->f32 | 1 bias+extra->f32 | 2 bias+gelu->half | 3 bias->half
//      4 bias+extra -> transposed store to (B,C,T,V) fp32 out
#define SA 40
#define SB 136
template<int EPI>
__global__ __launch_bounds__(256, 2) void k_gemm_h(const __half* __restrict__ A,
                                                   const __half2* __restrict__ Bp,
                                                   const float* __restrict__ bias,
                                                   const float* __restrict__ extra,
                                                   void* __restrict__ Cout,
                                                   int M, int N, int K) {
    __shared__ __align__(16) __half  As[3][128*SA];
    __shared__ __align__(16) __half2 Bs[3][16*SB];
    int tid = threadIdx.x, lane = tid & 31, warp = tid >> 5;
    int wm = warp >> 2, wn = warp & 3;
    int m0 = blockIdx.y * 128, n0 = blockIdx.x * 128;
    int r = lane >> 2, c = lane & 3;

    float acc[4][4][4];
    #pragma unroll
    for (int i = 0; i < 4; i++)
        #pragma unroll
        for (int j = 0; j < 4; j++)
            #pragma unroll
            for (int q = 0; q < 4; q++) acc[i][j][q] = 0.f;

    auto stage = [&](int s, int k0) {
        #pragma unroll
        for (int hh = 0; hh < 2; hh++) {
            int ch = tid + hh*256;
            int row = ch >> 2, seg = ch & 3;
            cpa16(sptr(&As[s][row*SA + seg*8]),
                  A + (size_t)(m0+row)*K + k0 + seg*8);
        }
        int k20 = k0 >> 1;
        #pragma unroll
        for (int hh = 0; hh < 2; hh++) {
            int ch = tid + hh*256;
            int k2 = ch >> 5, seg = ch & 31;
            cpa16(sptr(&Bs[s][k2*SB + seg*4]),
                  Bp + (size_t)(k20+k2)*N + n0 + seg*4);
        }
    };

    int nt = K >> 5;
    stage(0, 0);
    asm volatile("cp.async.commit_group;\n");
    stage(1, 32);
    asm volatile("cp.async.commit_group;\n");

    int lrow = (lane & 7) + ((lane >> 3) & 1)*8;
    int lcol = ((lane >> 4) & 1)*8;

    for (int t = 0; t < nt; t++) {
        if (t+1 < nt) asm volatile("cp.async.wait_group 1;\n");
        else          asm volatile("cp.async.wait_group 0;\n");
        __syncthreads();
        int s = t % 3;
        #pragma unroll
        for (int kk = 0; kk < 32; kk += 16) {
            unsigned af[4][4];
            #pragma unroll
            for (int i = 0; i < 4; i++) {
                int row = wm*64 + i*16 + lrow;
                unsigned ad = sptr(&As[s][row*SA + kk + lcol]);
                asm volatile("ldmatrix.sync.aligned.m8n8.x4.shared.b16 {%0,%1,%2,%3}, [%4];"
                    : "=r"(af[i][0]), "=r"(af[i][1]), "=r"(af[i][2]), "=r"(af[i][3])
                    : "r"(ad));
            }
            int kk2 = kk >> 1;
            unsigned bf[4][2];
            #pragma unroll
            for (int j = 0; j < 4; j++) {
                int nb = wn*32 + j*8 + r;
                bf[j][0] = *(const unsigned*)&Bs[s][(kk2+c  )*SB + nb];
                bf[j][1] = *(const unsigned*)&Bs[s][(kk2+c+4)*SB + nb];
            }
            #pragma unroll
            for (int i = 0; i < 4; i++)
                #pragma unroll
                for (int j = 0; j < 4; j++) {
                    asm volatile(
                        "mma.sync.aligned.m16n8k16.row.col.f32.f16.f16.f32 "
                        "{%0,%1,%2,%3}, {%4,%5,%6,%7}, {%8,%9}, {%0,%1,%2,%3};"
                        : "+f"(acc[i][j][0]), "+f"(acc[i][j][1]),
                          "+f"(acc[i][j][2]), "+f"(acc[i][j][3])
                        : "r"(af[i][0]), "r"(af[i][1]), "r"(af[i][2]), "r"(af[i][3]),
                          "r"(bf[j][0]), "r"(bf[j][1]));
                }
        }
        if (t+2 < nt) {
            stage((t+2) % 3, (t+2)*32);
            asm volatile("cp.async.commit_group;\n");
        }
    }

    if (EPI == 4) {
        // transposed epilogue: out is (B,C,T,V) fp32; for fixed col, rows contiguous
        float* tb = (float*)&As[0][0];     // 128 cols x (16 rows, stride 20) = 10 KB
        int bidx = m0 / TV;
        int rem0 = m0 % TV;
        #pragma unroll 1
        for (int wmt = 0; wmt < 2; wmt++) {
            #pragma unroll 1
            for (int i = 0; i < 4; i++) {
                __syncthreads();
                if (wm == wmt) {
                    #pragma unroll
                    for (int j = 0; j < 4; j++) {
                        int colb = wn*32 + j*8 + c*2;
                        float b0 = bias[n0+colb], b1 = bias[n0+colb+1];
                        #pragma unroll
                        for (int hh = 0; hh < 2; hh++) {
                            int rl = r + hh*8;
                            size_t mrow = (size_t)(m0 + wmt*64 + i*16 + rl);
                            const float2 e = *(const float2*)&extra[mrow*N + n0 + colb];
                            tb[colb*20 + rl]     = acc[i][j][2*hh]   + b0 + e.x;
                            tb[(colb+1)*20 + rl] = acc[i][j][2*hh+1] + b1 + e.y;
                        }
                    }
                }
                __syncthreads();
                int col = tid >> 1, rh = tid & 1;
                int cg = n0 + col;
                int rowbase = wmt*64 + i*16 + rh*8;
                float4 o1 = *(float4*)&tb[col*20 + rh*8];
                float4 o2 = *(float4*)&tb[col*20 + rh*8 + 4];
                size_t oaddr = (size_t)bidx*CDIM*TV + (size_t)cg*TV + rem0 + rowbase;
                *(float4*)&((float*)Cout)[oaddr]     = o1;
                *(float4*)&((float*)Cout)[oaddr + 4] = o2;
            }
        }
        return;
    }

    #pragma unroll
    for (int i = 0; i < 4; i++) {
        #pragma unroll
        for (int j = 0; j < 4; j++) {
            int row0 = m0 + wm*64 + i*16 + r;
            int col  = n0 + wn*32 + j*8 + c*2;
            float b0 = bias[col], b1 = bias[col+1];
            #pragma unroll
            for (int hh = 0; hh < 2; hh++) {
                size_t mrow = (size_t)(row0 + hh*8);
                float v0 = acc[i][j][2*hh+0] + b0;
                float v1 = acc[i][j][2*hh+1] + b1;
                if (EPI == 1) {
                    const float2 e = *(const float2*)&extra[mrow*N + col];
                    v0 += e.x; v1 += e.y;
                }
                if (EPI == 2) {
                    v0 = 0.5f * v0 * (1.0f + erff(v0 * 0.70710678118654752f));
                    v1 = 0.5f * v1 * (1.0f + erff(v1 * 0.70710678118654752f));
                }
                if (EPI == 2 || EPI == 3) {
                    *(__half2*)((__half*)Cout + mrow*N + col) = __floats2half2_rn(v0, v1);
                } else {
                    float2 o; o.x = v0; o.y = v1;
                    *(float2*)((float*)Cout + mrow*N + col) = o;
                }
            }
        }
    }
}

// ---------------- gconv branch: channels 0..63 (reads h_f half) ----------------
__global__ __launch_bounds__(256) void k_gconv(const float* __restrict__ gw) {
    int bt = blockIdx.x;
    __shared__ float fg[VDIM][64];
    int tid = threadIdx.x;
    size_t tok0 = (size_t)bt * VDIM;
    for (int i = tid; i < VDIM*32; i += 256) {
        int u = i >> 5, q = i & 31;
        __half2 hv = *((const __half2*)(h_f + (tok0+u)*C2) + q);
        float2 f2 = __half22float2(hv);
        fg[u][q*2] = f2.x; fg[u][q*2+1] = f2.y;
    }
    __syncthreads();
    for (int i = tid; i < VDIM*8; i += 256) {
        int v = i >> 3, g = i & 7;
        const float* gwp = gw + ((size_t)g*VDIM + v)*VDIM;
        float acc[8];
        #pragma unroll
        for (int o = 0; o < 8; o++) acc[o] = 0.f;
        #pragma unroll 5
        for (int u2 = 0; u2 < VDIM/2; u2++) {
            float2 wv = *(const float2*)&gwp[u2*2];
            float4 a0 = *(const float4*)&fg[2*u2][g*8];
            float4 a1 = *(const float4*)&fg[2*u2][g*8+4];
            float4 b0 = *(const float4*)&fg[2*u2+1][g*8];
            float4 b1 = *(const float4*)&fg[2*u2+1][g*8+4];
            acc[0] += wv.x*a0.x + wv.y*b0.x;
            acc[1] += wv.x*a0.y + wv.y*b0.y;
            acc[2] += wv.x*a0.z + wv.y*b0.z;
            acc[3] += wv.x*a0.w + wv.y*b0.w;
            acc[4] += wv.x*a1.x + wv.y*b1.x;
            acc[5] += wv.x*a1.y + wv.y*b1.y;
            acc[6] += wv.x*a1.z + wv.y*b1.z;
            acc[7] += wv.x*a1.w + wv.y*b1.w;
        }
        __half* dst = h_cat + (tok0+v)*CDIM + g*8;
        #pragma unroll
        for (int o = 0; o < 8; o += 2)
            *(__half2*)&dst[o] = __floats2half2_rn(acc[o], acc[o+1]);
    }
}

// ---------------- grouped temporal conv per (b,v): channels 64..127 ----------------
__global__ __launch_bounds__(256) void k_tconv2(const float* __restrict__ w,
                                                const float* __restrict__ bias) {
    int blk = blockIdx.x;             // B*V
    int bb = blk / VDIM, v = blk % VDIM;
    __shared__ float X[TDIM][65];     // [t][ch]  (stride 65: conflict-free)
    __shared__ float ws[56*64];       // [ic*7+dt][o]
    int tid = threadIdx.x;
    for (int i = tid; i < 64*56; i += 256) {
        int o = i / 56, rr = i % 56;
        ws[rr*64 + o] = w[i];
    }
    for (int i = tid; i < TDIM*32; i += 256) {
        int t = i >> 5, q = i & 31;
        __half2 hv = *((const __half2*)(h_f + ((size_t)(bb*TDIM + t)*VDIM + v)*C2 + 64) + q);
        float2 f2 = __half22float2(hv);
        X[t][q*2] = f2.x; X[t][q*2+1] = f2.y;
    }
    __syncthreads();
    int t = tid & 63, og = tid >> 6;
    size_t tokbase = ((size_t)(bb*TDIM + t)*VDIM + v)*CDIM + 64;
    #pragma unroll
    for (int hg = 0; hg < 2; hg++) {
        int g = og*2 + hg;
        float acc8[8];
        #pragma unroll
        for (int k = 0; k < 8; k++) acc8[k] = bias[g*8 + k];
        #pragma unroll
        for (int dt = 0; dt < 7; dt++) {
            int tt = t + dt - 3;
            if (tt < 0 || tt >= TDIM) continue;
            float xv[8];
            #pragma unroll
            for (int ic = 0; ic < 8; ic++) xv[ic] = X[tt][g*8 + ic];
            #pragma unroll
            for (int ic = 0; ic < 8; ic++) {
                const float* wr = &ws[(ic*7 + dt)*64 + g*8];
                #pragma unroll
                for (int k = 0; k < 8; k++) acc8[k] += xv[ic] * wr[k];
            }
        }
        __half* dst = h_cat + tokbase + g*8;
        #pragma unroll
        for (int k = 0; k < 8; k += 2)
            *(__half2*)&dst[k] = __floats2half2_rn(acc8[k], acc8[k+1]);
    }
}

// ---------------- windowed hyperbolic linear attention: channels 128..255 ----------------
__global__ __launch_bounds__(128) void k_attn() {
    int wb = blockIdx.x;
    int mode = wb / (BDIM*40);
    int rem  = wb % (BDIM*40);
    int bb = rem / 40;
    int wwin = rem % 40;
    int i0 = wwin / 5, i1 = wwin % 5;

    __shared__ float X[80][97];
    __shared__ float kv[4][8][8];
    __shared__ float O[80][33];
    __shared__ int   toks[80];
    int tid = threadIdx.x;

    if (tid < 80) {
        int a = tid / 10, e = tid % 10;
        int t, v;
        if      (mode == 0) { t = i0*8 + a; v = i1*10 + e; }
        else if (mode == 1) { t = i0*8 + a; v = e*5 + i1;  }
        else if (mode == 2) { t = a*8 + i0; v = i1*10 + e; }
        else                { t = a*8 + i0; v = e*5 + i1;  }
        toks[tid] = (bb*TDIM + t)*VDIM + v;
    }
    __syncthreads();

    int cb = 128 + mode*96;
    for (int i = tid; i < 80*96; i += 128) {
        int n = i / 96, c = i % 96;
        X[n][c] = __half2float(h_f[(size_t)toks[n]*C2 + cb + c]);
    }
    __syncthreads();

    if (tid < 80) {
        float sq = 0.f;
        #pragma unroll 8
        for (int c = 0; c < 96; c++) { float q = X[tid][c]; sq += q*q; }
        float nrm = fmaxf(sqrtf(sq), 1e-10f);
        float sc = tanhf(nrm) / nrm;
        #pragma unroll 8
        for (int c = 0; c < 96; c++) X[tid][c] *= sc;
    }
    __syncthreads();

    for (int i = tid; i < 256; i += 128) {
        int h = i >> 6, d = (i >> 3) & 7, e = i & 7;
        float acc = 0.f;
        for (int n = 0; n < 80; n++)
            acc += X[n][32 + h*8 + d] * X[n][64 + h*8 + e];
        kv[h][d][e] = acc;
    }
    __syncthreads();

    if (tid < 32) {
        int h = tid >> 3, d = tid & 7;
        float mx = -1e30f;
        #pragma unroll
        for (int e = 0; e < 8; e++) mx = fmaxf(mx, kv[h][d][e]);
        float s = 0.f;
        #pragma unroll
        for (int e = 0; e < 8; e++) { float q = expf(kv[h][d][e] - mx); s += q; kv[h][d][e] = q; }
        float inv = 1.0f / s;
        #pragma unroll
        for (int e = 0; e < 8; e++) kv[h][d][e] *= inv;
    }
    __syncthreads();

    for (int i = tid; i < 80*32; i += 128) {
        int n = i >> 5, o = i & 31;
        int h = o >> 3, mm = o & 7;
        float acc = 0.f;
        #pragma unroll
        for (int e = 0; e < 8; e++) acc += X[n][h*8 + e] * kv[h][mm][e];
        O[n][o] = 0.5f * acc;
    }
    __syncthreads();

    if (tid < 80) {
        float sq = 0.f;
        #pragma unroll
        for (int c = 0; c < 32; c++) { float q = O[tid][c]; sq += q*q; }
        float nrm = fminf(fmaxf(sqrtf(sq), 1e-10f), 1.0f - 1e-5f);
        float sc = atanhf(-nrm) / nrm;
        __half* dst = h_cat + (size_t)toks[tid]*CDIM + 128 + mode*32;
        #pragma unroll
        for (int c = 0; c < 32; c++) dst[c] = __float2half(O[tid][c] * sc);
    }
}

// ---------------- launch ----------------
extern "C" void kernel_launch(void* const* d_in, const int* in_sizes, int n_in,
                              void* d_out, int out_size) {
    const float* x       = (const float*)d_in[0];
    const float* n1w     = (const float*)d_in[1];
    const float* n1b     = (const float*)d_in[2];
    const float* map_w   = (const float*)d_in[3];
    const float* map_b   = (const float*)d_in[4];
    const float* gconv   = (const float*)d_in[5];
    const float* tconv_w = (const float*)d_in[6];
    const float* tconv_b = (const float*)d_in[7];
    const float* proj_w  = (const float*)d_in[8];
    const float* proj_b  = (const float*)d_in[9];
    const float* n2w     = (const float*)d_in[10];
    const float* n2b     = (const float*)d_in[11];
    const float* mlp_w1  = (const float*)d_in[12];
    const float* mlp_b1  = (const float*)d_in[13];
    const float* mlp_w2  = (const float*)d_in[14];
    const float* mlp_b2  = (const float*)d_in[15];
    float* out = (float*)d_out;

    float *p_xt, *p_out1;
    __half *p_f, *p_xln, *p_cat, *p_ln2, *p_h;
    __half2 *p_wmap, *p_wproj, *p_wm1, *p_wm2;
    cudaGetSymbolAddress((void**)&p_xt,   g_xt);
    cudaGetSymbolAddress((void**)&p_out1, g_out1);
    cudaGetSymbolAddress((void**)&p_f,    h_f);
    cudaGetSymbolAddress((void**)&p_xln,  h_xln);
    cudaGetSymbolAddress((void**)&p_cat,  h_cat);
    cudaGetSymbolAddress((void**)&p_ln2,  h_ln2);
    cudaGetSymbolAddress((void**)&p_h,    h_h);
    cudaGetSymbolAddress((void**)&p_wmap,  w_map);
    cudaGetSymbolAddress((void**)&p_wproj, w_proj);
    cudaGetSymbolAddress((void**)&p_wm1,   w_m1);
    cudaGetSymbolAddress((void**)&p_wm2,   w_m2);

    k_wpair<<<(CDIM/2*C2  + 255)/256, 256>>>(map_w,  p_wmap,  CDIM, C2);
    k_wpair<<<(CDIM/2*CDIM+ 255)/256, 256>>>(proj_w, p_wproj, CDIM, CDIM);
    k_wpair<<<(CDIM/2*C4  + 255)/256, 256>>>(mlp_w1, p_wm1,   CDIM, C4);
    k_wpair<<<(C4/2*CDIM  + 255)/256, 256>>>(mlp_w2, p_wm2,   C4,   CDIM);

    k_transln<<<BDIM*TDIM, 256>>>(x, n1w, n1b);
    k_gemm_h<3><<<dim3(C2/128, TOK/128), 256>>>(p_xln, p_wmap, map_b, nullptr, p_f, TOK, C2, CDIM);
    k_gconv<<<BDIM*TDIM, 256>>>(gconv);
    k_tconv2<<<BDIM*VDIM, 256>>>(tconv_w, tconv_b);
    k_attn<<<4*BDIM*40, 128>>>();
    k_gemm_h<1><<<dim3(CDIM/128, TOK/128), 256>>>(p_cat, p_wproj, proj_b, p_xt, p_out1, TOK, CDIM, CDIM);
    k_ln<<<TOK, 256>>>(p_out1, p_ln2, n2w, n2b);
    k_gemm_h<2><<<dim3(C4/128, TOK/128), 256>>>(p_ln2, p_wm1, mlp_b1, nullptr, p_h, TOK, C4, CDIM);
    k_gemm_h<4><<<dim3(CDIM/128, TOK/128), 256>>>(p_h, p_wm2, mlp_b2, p_out1, out, TOK, CDIM, C4);
}